// round 6
// baseline (speedup 1.0000x reference)
#include <cuda_runtime.h>
#include <cstdint>

// ---------------- problem constants ----------------
namespace {
constexpr int CB  = 4;      // batch
constexpr int CS  = 1024;   // seq
constexpr int CD  = 1280;   // model dim
constexpr int CH  = 16;     // heads
constexpr int CHD = 80;     // head dim
constexpr int CM  = CB * CS;          // 4096 rows
constexpr int CNQKV = 3 * CD;         // 3840

// dense GEMM tiling (CTA 256x128, 8 warps, warp tile 64x64)
constexpr int PAW = 36;                       // smem pitch (u32) per 32-k row
constexpr int SSTG = 256 * PAW + 128 * PAW;   // stage stride in u32 = 13824
constexpr int GEMM_SMEM = 2 * SSTG * 4;       // 110,592 B

// attention smem pitches (u32 units)
constexpr int PQ = 84;
constexpr int PK = 72;
constexpr int PV = 88;
constexpr int PP = 68;
constexpr int ATTN_U32 = 64*PQ + 80*PK + 64*PV + 64*PP + 128;
constexpr int ATTN_SMEM = ATTN_U32 * 4;   // 84,992 B
}
#define ATTN_SCALE 0.11180339887498948f  // 80^-0.5

// ---------------- scratch (device globals; no allocs allowed) ----------------
__device__ __align__(16) float g_q[CB * CH * CS * CHD];     // [b,h,s,d]
__device__ __align__(16) float g_k[CB * CH * CS * CHD];
__device__ __align__(16) float g_v[CB * CH * CS * CHD];
__device__ __align__(16) float g_ctx[CM * CD];              // [b,s, h*HD+d]
// tf32 pre-converted, k-permuted operands
__device__ __align__(16) uint32_t g_xp[CM * CD];            // [m][k']
__device__ __align__(16) uint32_t g_ctxp[CM * CD];          // [m][k']
__device__ __align__(16) uint32_t g_wqkvp[CNQKV * CD];      // [n][k']  (transposed)
__device__ __align__(16) uint32_t g_wprojp[CD * CD];        // [n][k']

// ---------------- tf32 helpers ----------------
__device__ __forceinline__ uint32_t f2tf32(float f) {
    uint32_t u;
    asm("cvt.rna.tf32.f32 %0, %1;" : "=r"(u) : "f"(f));
    return u;
}
__device__ __forceinline__ void mma_tf32(float c[4],
                                         uint32_t a0, uint32_t a1, uint32_t a2, uint32_t a3,
                                         uint32_t b0, uint32_t b1) {
    asm volatile(
        "mma.sync.aligned.m16n8k8.row.col.f32.tf32.tf32.f32 "
        "{%0,%1,%2,%3}, {%4,%5,%6,%7}, {%8,%9}, {%0,%1,%2,%3};"
        : "+f"(c[0]), "+f"(c[1]), "+f"(c[2]), "+f"(c[3])
        : "r"(a0), "r"(a1), "r"(a2), "r"(a3), "r"(b0), "r"(b1));
}
__device__ __forceinline__ uint32_t smem_u32(const void* p) {
    uint32_t a;
    asm("{ .reg .u64 t; cvta.to.shared.u64 t, %1; cvt.u32.u64 %0, t; }"
        : "=r"(a) : "l"(p));
    return a;
}

// ============================================================================
// Pre-convert kernels.
// k-permutation within each 32-block: k' = (k%4)*8 + k/4  (inverse k = (k'%8)*4 + k'/8)
// ============================================================================
// A-side: [M][K] fp32 -> [M][K] tf32 permuted. MODE 0: x (param), MODE 1: g_ctx.
template <int MODE>
__global__ void __launch_bounds__(256)
permA(const float* __restrict__ inp)
{
    const float* __restrict__ in = (MODE == 1) ? (const float*)g_ctx : inp;
    uint32_t* __restrict__ out = (MODE == 1) ? g_ctxp : g_xp;
    const int i = blockIdx.x * 256 + threadIdx.x;      // output float4 index
    const int m  = i / (CD / 4);
    const int c4 = i - m * (CD / 4);
    const int kb = c4 >> 3, q = c4 & 7;
    const float* src = in + (size_t)m * CD + kb * 32 + 16 * (q & 1) + (q >> 1);
    uint4 o = { f2tf32(src[0]), f2tf32(src[4]), f2tf32(src[8]), f2tf32(src[12]) };
    reinterpret_cast<uint4*>(out)[i] = o;
}

// B-side: W [K][N] fp32 -> [N][K] tf32 permuted (transpose). MODE 0: Wqkv, MODE 1: Wproj.
template <int MODE>
__global__ void transB(const float* __restrict__ W)
{
    uint32_t* __restrict__ out = MODE ? g_wprojp : g_wqkvp;
    const int N = MODE ? CD : CNQKV;
    __shared__ float tile[32][33];
    const int tx = threadIdx.x, ty = threadIdx.y;
    const int nb = blockIdx.x, kb = blockIdx.y;
    #pragma unroll
    for (int r = 0; r < 4; r++) {
        const int kl = ty + 8 * r;
        tile[kl][tx] = W[(size_t)(kb * 32 + kl) * N + nb * 32 + tx];
    }
    __syncthreads();
    const int ksrc = ((tx & 7) << 2) + (tx >> 3);   // inverse perm
    #pragma unroll
    for (int r = 0; r < 4; r++) {
        const int nl = ty + 8 * r;
        out[(size_t)(nb * 32 + nl) * CD + kb * 32 + tx] = f2tf32(tile[ksrc][nl]);
    }
}

// ============================================================================
// tf32 mma.sync GEMM v2: C(256x128) = A @ W^T-stored + bias.
// Operands pre-converted/permuted. cp.async double-buffered; fragment loads
// are conflict-free LDS.128 thanks to the k'-permutation.
// 8 warps, warp grid 4(m) x 2(n), warp tile 64x64 (4x8 m16n8k8 atoms).
// MODE 0: A=g_xp, B=g_wqkvp, scatter into g_q/g_k/g_v.  MODE 1: A=g_ctxp, B=g_wprojp -> out.
// ============================================================================
template <int MODE>
__global__ void __launch_bounds__(256)
gemm_tc2(const float* __restrict__ bias, float* __restrict__ out, int N)
{
    const uint32_t* __restrict__ Ap = MODE ? g_ctxp : g_xp;
    const uint32_t* __restrict__ Bp = MODE ? g_wprojp : g_wqkvp;
    constexpr int K = CD;

    extern __shared__ uint32_t smu[];
    const uint32_t smbase = smem_u32(smu);

    const int tid  = threadIdx.x;
    const int wid  = tid >> 5;
    const int lane = tid & 31;
    const int g    = lane >> 2;
    const int t    = lane & 3;
    const int wm   = wid & 3;        // 4 m-warps (64 rows each)
    const int wn   = wid >> 2;       // 2 n-warps (64 cols each)
    const int m0   = blockIdx.y * 256;
    const int n0   = blockIdx.x * 128;

    float cf[4][8][4];
    #pragma unroll
    for (int im = 0; im < 4; im++)
        #pragma unroll
        for (int in = 0; in < 8; in++)
            #pragma unroll
            for (int r = 0; r < 4; r++) cf[im][in][r] = 0.f;

    auto issue = [&](int c, int p) {
        const uint32_t abase = smbase + (uint32_t)p * SSTG * 4;
        const uint32_t bbase = abase + 256 * PAW * 4;
        const int k0 = c * 32;
        #pragma unroll
        for (int i = 0; i < 8; i++) {          // A: 256 rows x 8 segs
            const int s = tid + 256 * i;
            const int m = s >> 3, q = s & 7;
            const uint32_t dst = abase + (uint32_t)(m * PAW + q * 4) * 4;
            const uint32_t* src = Ap + (size_t)(m0 + m) * K + k0 + q * 4;
            asm volatile("cp.async.cg.shared.global [%0], [%1], 16;"
                         :: "r"(dst), "l"(src));
        }
        #pragma unroll
        for (int i = 0; i < 4; i++) {          // B: 128 rows x 8 segs
            const int s = tid + 256 * i;
            const int n = s >> 3, q = s & 7;
            const uint32_t dst = bbase + (uint32_t)(n * PAW + q * 4) * 4;
            const uint32_t* src = Bp + (size_t)(n0 + n) * K + k0 + q * 4;
            asm volatile("cp.async.cg.shared.global [%0], [%1], 16;"
                         :: "r"(dst), "l"(src));
        }
        asm volatile("cp.async.commit_group;" ::: "memory");
    };

    const int NCH = K / 32;   // 40
    issue(0, 0);

    for (int c = 0; c < NCH; c++) {
        const int p = c & 1;
        if (c + 1 < NCH) {
            issue(c + 1, 1 - p);
            asm volatile("cp.async.wait_group 1;" ::: "memory");
        } else {
            asm volatile("cp.async.wait_group 0;" ::: "memory");
        }
        __syncthreads();

        const uint32_t* As = smu + p * SSTG;
        const uint32_t* Bs = As + 256 * PAW;

        #pragma unroll
        for (int kh = 0; kh < 2; kh++) {
            uint4 a[4][2], b[8];
            #pragma unroll
            for (int im = 0; im < 4; im++) {
                const int row = wm * 64 + im * 16 + g;
                a[im][0] = *reinterpret_cast<const uint4*>(As + row * PAW + t * 8 + kh * 4);
                a[im][1] = *reinterpret_cast<const uint4*>(As + (row + 8) * PAW + t * 8 + kh * 4);
            }
            #pragma unroll
            for (int in = 0; in < 8; in++) {
                const int n = wn * 64 + in * 8 + g;
                b[in] = *reinterpret_cast<const uint4*>(Bs + n * PAW + t * 8 + kh * 4);
            }
            // element e of each float4 corresponds to k' = t*8 + kh*4 + e:
            //   e0=2*ks2 -> (a0,b0), e0+1 -> (a2,b1)
            #pragma unroll
            for (int ks2 = 0; ks2 < 2; ks2++) {
                #pragma unroll
                for (int im = 0; im < 4; im++) {
                    const uint32_t a0 = ks2 ? a[im][0].z : a[im][0].x;
                    const uint32_t a2 = ks2 ? a[im][0].w : a[im][0].y;
                    const uint32_t a1 = ks2 ? a[im][1].z : a[im][1].x;
                    const uint32_t a3 = ks2 ? a[im][1].w : a[im][1].y;
                    #pragma unroll
                    for (int in = 0; in < 8; in++) {
                        const uint32_t b0 = ks2 ? b[in].z : b[in].x;
                        const uint32_t b1 = ks2 ? b[in].w : b[in].y;
                        mma_tf32(cf[im][in], a0, a1, a2, a3, b0, b1);
                    }
                }
            }
        }
        __syncthreads();
    }

    // ---- epilogue: +bias, float2 stores ----
    #pragma unroll
    for (int im = 0; im < 4; im++) {
        #pragma unroll
        for (int in = 0; in < 8; in++) {
            const int mrow0 = m0 + wm * 64 + im * 16 + g;
            const int ncol  = n0 + wn * 64 + in * 8 + 2 * t;
            const float2 bb = *reinterpret_cast<const float2*>(bias + ncol);
            #pragma unroll
            for (int h2 = 0; h2 < 2; h2++) {
                const int m = mrow0 + h2 * 8;
                float2 v;
                v.x = cf[im][in][h2 * 2 + 0] + bb.x;
                v.y = cf[im][in][h2 * 2 + 1] + bb.y;
                if (MODE == 0) {
                    const int b = m >> 10;
                    const int s = m & 1023;
                    const int which = ncol / CD;        // 0=q 1=k 2=v
                    const int r = ncol - which * CD;
                    const int h = r / CHD;
                    const int d = r - h * CHD;
                    const size_t di = ((size_t)(b * CH + h) * CS + s) * CHD + d;
                    float* dst = (which == 0) ? g_q : (which == 1) ? g_k : g_v;
                    *reinterpret_cast<float2*>(dst + di) = v;
                } else {
                    *reinterpret_cast<float2*>(out + (size_t)m * CD + ncol) = v;
                }
            }
        }
    }
}

// ============================================================================
// RoPE (half-rotation), unchanged.
// ============================================================================
__global__ void __launch_bounds__(256)
rope_kernel(const float* __restrict__ cosb, const float* __restrict__ sinb)
{
    const int idx = blockIdx.x * blockDim.x + threadIdx.x;
    constexpr int TOT = CB * CH * CS * (CHD / 2);
    if (idx >= TOT) return;
    const int d  = idx % (CHD / 2);
    const int s  = (idx / (CHD / 2)) % CS;
    const int bh = idx / ((CHD / 2) * CS);

    const float c  = cosb[s * CHD + d];
    const float sn = sinb[s * CHD + d];
    const size_t base = ((size_t)bh * CS + s) * CHD;

    float q1 = g_q[base + d], q2 = g_q[base + d + 40];
    g_q[base + d]      = q1 * c - q2 * sn;
    g_q[base + d + 40] = q2 * c + q1 * sn;

    float k1 = g_k[base + d], k2 = g_k[base + d + 40];
    g_k[base + d]      = k1 * c - k2 * sn;
    g_k[base + d + 40] = k2 * c + k1 * sn;
}

// ============================================================================
// Fused flash attention, tf32 mma.sync (unchanged from R5).
// ============================================================================
__global__ void __launch_bounds__(256)
attn_tc()
{
    extern __shared__ uint32_t smu[];
    uint32_t* Qs = smu;
    uint32_t* Kt = Qs + 64 * PQ;
    uint32_t* Vs = Kt + 80 * PK;
    float*    Ps = (float*)(Vs + 64 * PV);
    float*    sAlpha = Ps + 64 * PP;
    float*    sL     = sAlpha + 64;

    const int tid  = threadIdx.x;
    const int wid  = tid >> 5;
    const int lane = tid & 31;
    const int g    = lane >> 2;
    const int t    = lane & 3;
    const int wm   = wid & 1;
    const int wn   = wid >> 1;
    const int wq   = wid & 3;
    const int wd   = wid >> 2;
    const int srow = tid >> 2;
    const int sseg = tid & 3;

    const int bh = blockIdx.y;
    const int q0 = blockIdx.x * 64;

    const float* __restrict__ Qg = g_q + (size_t)bh * CS * CHD;
    const float* __restrict__ Kg = g_k + (size_t)bh * CS * CHD;
    const float* __restrict__ Vg = g_v + (size_t)bh * CS * CHD;

    for (int p = tid; p < 64 * CHD; p += 256) {
        const int r = p / CHD, c = p - r * CHD;
        Qs[r * PQ + c] = f2tf32(Qg[(size_t)(q0 + r) * CHD + c] * ATTN_SCALE);
    }

    float m_ = -1e30f, l_ = 0.f;
    float of[5][4];
    #pragma unroll
    for (int i = 0; i < 5; i++)
        #pragma unroll
        for (int r = 0; r < 4; r++) of[i][r] = 0.f;

    for (int tt = 0; tt < CS; tt += 64) {
        __syncthreads();
        for (int p = tid; p < 64 * CHD; p += 256) {
            const int r = p / CHD, c = p - r * CHD;
            Kt[c * PK + r] = f2tf32(Kg[(size_t)(tt + r) * CHD + c]);
            Vs[r * PV + c] = f2tf32(Vg[(size_t)(tt + r) * CHD + c]);
        }
        __syncthreads();

        float sacc[2][2][4];
        #pragma unroll
        for (int im = 0; im < 2; im++)
            #pragma unroll
            for (int in = 0; in < 2; in++)
                #pragma unroll
                for (int r = 0; r < 4; r++) sacc[im][in][r] = 0.f;

        #pragma unroll
        for (int ks = 0; ks < 10; ks++) {
            uint32_t af[2][4], bf[2][2];
            #pragma unroll
            for (int im = 0; im < 2; im++) {
                const int row = wm * 32 + im * 16 + g;
                const int col = ks * 8 + t;
                af[im][0] = Qs[row * PQ + col];
                af[im][1] = Qs[(row + 8) * PQ + col];
                af[im][2] = Qs[row * PQ + col + 4];
                af[im][3] = Qs[(row + 8) * PQ + col + 4];
            }
            #pragma unroll
            for (int in = 0; in < 2; in++) {
                const int n = wn * 16 + in * 8 + g;
                bf[in][0] = Kt[(ks * 8 + t) * PK + n];
                bf[in][1] = Kt[(ks * 8 + t + 4) * PK + n];
            }
            #pragma unroll
            for (int im = 0; im < 2; im++)
                #pragma unroll
                for (int in = 0; in < 2; in++)
                    mma_tf32(sacc[im][in], af[im][0], af[im][1], af[im][2], af[im][3],
                             bf[in][0], bf[in][1]);
        }
        #pragma unroll
        for (int im = 0; im < 2; im++) {
            const int r0 = wm * 32 + im * 16;
            #pragma unroll
            for (int in = 0; in < 2; in++) {
                const int cl = wn * 16 + in * 8 + 2 * t;
                *reinterpret_cast<float2*>(&Ps[(r0 + g) * PP + cl]) =
                    make_float2(sacc[im][in][0], sacc[im][in][1]);
                *reinterpret_cast<float2*>(&Ps[(r0 + g + 8) * PP + cl]) =
                    make_float2(sacc[im][in][2], sacc[im][in][3]);
            }
        }
        __syncthreads();

        {
            float* prow = Ps + srow * PP + sseg * 16;
            float vals[16];
            float mx = -1e30f;
            #pragma unroll
            for (int j = 0; j < 16; j++) { vals[j] = prow[j]; mx = fmaxf(mx, vals[j]); }
            mx = fmaxf(mx, __shfl_xor_sync(0xffffffffu, mx, 1));
            mx = fmaxf(mx, __shfl_xor_sync(0xffffffffu, mx, 2));
            const float mnew  = fmaxf(m_, mx);
            const float alpha = __expf(m_ - mnew);
            float rs = 0.f;
            uint32_t* prow_u = reinterpret_cast<uint32_t*>(prow);
            #pragma unroll
            for (int j = 0; j < 16; j++) {
                const float pj = __expf(vals[j] - mnew);
                rs += pj;
                prow_u[j] = f2tf32(pj);
            }
            rs += __shfl_xor_sync(0xffffffffu, rs, 1);
            rs += __shfl_xor_sync(0xffffffffu, rs, 2);
            l_ = l_ * alpha + rs;
            m_ = mnew;
            if (sseg == 0) sAlpha[srow] = alpha;
        }
        __syncthreads();

        {
            const float aL = sAlpha[wq * 16 + g];
            const float aH = sAlpha[wq * 16 + g + 8];
            #pragma unroll
            for (int in = 0; in < 5; in++) {
                of[in][0] *= aL; of[in][1] *= aL;
                of[in][2] *= aH; of[in][3] *= aH;
            }
            const uint32_t* Pu = reinterpret_cast<const uint32_t*>(Ps);
            #pragma unroll
            for (int ks = 0; ks < 8; ks++) {
                const int row = wq * 16 + g;
                const int col = ks * 8 + t;
                uint32_t a0 = Pu[row * PP + col];
                uint32_t a1 = Pu[(row + 8) * PP + col];
                uint32_t a2 = Pu[row * PP + col + 4];
                uint32_t a3 = Pu[(row + 8) * PP + col + 4];
                #pragma unroll
                for (int in = 0; in < 5; in++) {
                    const int n = wd * 40 + in * 8 + g;
                    const uint32_t b0 = Vs[(ks * 8 + t) * PV + n];
                    const uint32_t b1 = Vs[(ks * 8 + t + 4) * PV + n];
                    mma_tf32(of[in], a0, a1, a2, a3, b0, b1);
                }
            }
        }
    }

    __syncthreads();
    if (sseg == 0) sL[srow] = l_;
    __syncthreads();

    const int b = bh >> 4, h = bh & 15;
    const float invL = 1.f / sL[wq * 16 + g];
    const float invH = 1.f / sL[wq * 16 + g + 8];
    const int rL = q0 + wq * 16 + g;
    const int rH = rL + 8;
    #pragma unroll
    for (int in = 0; in < 5; in++) {
        const int col = h * CHD + wd * 40 + in * 8 + 2 * t;
        *reinterpret_cast<float2*>(&g_ctx[((size_t)b * CS + rL) * CD + col]) =
            make_float2(of[in][0] * invL, of[in][1] * invL);
        *reinterpret_cast<float2*>(&g_ctx[((size_t)b * CS + rH) * CD + col]) =
            make_float2(of[in][2] * invH, of[in][3] * invH);
    }
}

// ============================================================================
// launch
// ============================================================================
extern "C" void kernel_launch(void* const* d_in, const int* in_sizes, int n_in,
                              void* d_out, int out_size)
{
    const float* x        = (const float*)d_in[0];
    const float* rope_cos = (const float*)d_in[1];
    const float* rope_sin = (const float*)d_in[2];
    const float* Wqkv     = (const float*)d_in[3];
    const float* bqkv     = (const float*)d_in[4];
    const float* Wproj    = (const float*)d_in[5];
    const float* bproj    = (const float*)d_in[6];
    float* out            = (float*)d_out;

    // 0) pre-convert / permute operands to tf32
    permA<0><<<CM * CD / 4 / 256, 256>>>(x);
    transB<0><<<dim3(CNQKV / 32, CD / 32), dim3(32, 8)>>>(Wqkv);
    transB<1><<<dim3(CD / 32, CD / 32), dim3(32, 8)>>>(Wproj);

    // 1) QKV projection -> g_q/g_k/g_v
    cudaFuncSetAttribute(gemm_tc2<0>, cudaFuncAttributeMaxDynamicSharedMemorySize, GEMM_SMEM);
    gemm_tc2<0><<<dim3(CNQKV / 128, CM / 256), 256, GEMM_SMEM>>>(bqkv, nullptr, CNQKV);

    // 2) RoPE on q,k
    {
        const int pairs = CB * CH * CS * (CHD / 2);
        rope_kernel<<<(pairs + 255) / 256, 256>>>(rope_cos, rope_sin);
    }

    // 3) fused flash attention -> g_ctx
    cudaFuncSetAttribute(attn_tc, cudaFuncAttributeMaxDynamicSharedMemorySize, ATTN_SMEM);
    attn_tc<<<dim3(CS / 64, CB * CH), 256, ATTN_SMEM>>>();

    // 4) convert ctx, then output projection -> d_out
    permA<1><<<CM * CD / 4 / 256, 256>>>(nullptr);
    cudaFuncSetAttribute(gemm_tc2<1>, cudaFuncAttributeMaxDynamicSharedMemorySize, GEMM_SMEM);
    gemm_tc2<1><<<dim3(CD / 128, CM / 256), 256, GEMM_SMEM>>>(bproj, out, CD);
}

// round 7
// speedup vs baseline: 1.0090x; 1.0090x over previous
#include <cuda_runtime.h>
#include <cstdint>

// ---------------- problem constants ----------------
namespace {
constexpr int CB  = 4;      // batch
constexpr int CS  = 1024;   // seq
constexpr int CD  = 1280;   // model dim
constexpr int CH  = 16;     // heads
constexpr int CHD = 80;     // head dim
constexpr int CM  = CB * CS;          // 4096 rows
constexpr int CNQKV = 3 * CD;         // 3840

// dense GEMM tiling (CTA 256x128, 8 warps, warp tile 64x64), 3-stage cp.async
constexpr int PAW = 36;                       // smem pitch (u32) per 32-k row
constexpr int SSTG = 256 * PAW + 128 * PAW;   // stage stride in u32 = 13824
constexpr int NSTAGE = 3;
constexpr int GEMM_SMEM = NSTAGE * SSTG * 4;  // 165,888 B

// attention smem pitches (u32 units)
constexpr int PQ = 84;
constexpr int PK = 72;
constexpr int PV = 88;
constexpr int PP = 68;
constexpr int ATTN_U32 = 64*PQ + 80*PK + 64*PV + 64*PP + 128;
constexpr int ATTN_SMEM = ATTN_U32 * 4;   // 84,992 B
}
#define ATTN_SCALE 0.11180339887498948f  // 80^-0.5

// ---------------- scratch (device globals; no allocs allowed) ----------------
__device__ __align__(16) float g_q[CB * CH * CS * CHD];     // [b,h,s,d]
__device__ __align__(16) float g_k[CB * CH * CS * CHD];
__device__ __align__(16) float g_v[CB * CH * CS * CHD];
// tf32 pre-converted, k-permuted operands
__device__ __align__(16) uint32_t g_xp[CM * CD];            // [m][k']
__device__ __align__(16) uint32_t g_ctxp[CM * CD];          // [m][k'] (written by attn)
__device__ __align__(16) uint32_t g_wqkvp[CNQKV * CD];      // [n][k']  (transposed)
__device__ __align__(16) uint32_t g_wprojp[CD * CD];        // [n][k']

// ---------------- tf32 helpers ----------------
__device__ __forceinline__ uint32_t f2tf32(float f) {
    uint32_t u;
    asm("cvt.rna.tf32.f32 %0, %1;" : "=r"(u) : "f"(f));
    return u;
}
__device__ __forceinline__ void mma_tf32(float c[4],
                                         uint32_t a0, uint32_t a1, uint32_t a2, uint32_t a3,
                                         uint32_t b0, uint32_t b1) {
    asm volatile(
        "mma.sync.aligned.m16n8k8.row.col.f32.tf32.tf32.f32 "
        "{%0,%1,%2,%3}, {%4,%5,%6,%7}, {%8,%9}, {%0,%1,%2,%3};"
        : "+f"(c[0]), "+f"(c[1]), "+f"(c[2]), "+f"(c[3])
        : "r"(a0), "r"(a1), "r"(a2), "r"(a3), "r"(b0), "r"(b1));
}
__device__ __forceinline__ uint32_t smem_u32(const void* p) {
    uint32_t a;
    asm("{ .reg .u64 t; cvta.to.shared.u64 t, %1; cvt.u32.u64 %0, t; }"
        : "=r"(a) : "l"(p));
    return a;
}
// k-permutation within each 32-block: k' = (k%4)*8 + k/4
__device__ __forceinline__ int kperm(int k) {
    const int kb = k >> 5, kl = k & 31;
    return kb * 32 + (kl & 3) * 8 + (kl >> 2);
}

// ============================================================================
// Pre-convert kernels (x and weights only; ctx is produced permuted by attn).
// ============================================================================
__global__ void __launch_bounds__(256)
permA0(const float* __restrict__ in)
{
    const int i = blockIdx.x * 256 + threadIdx.x;      // output float4 index
    const int m  = i / (CD / 4);
    const int c4 = i - m * (CD / 4);
    const int kb = c4 >> 3, q = c4 & 7;
    const float* src = in + (size_t)m * CD + kb * 32 + 16 * (q & 1) + (q >> 1);
    uint4 o = { f2tf32(src[0]), f2tf32(src[4]), f2tf32(src[8]), f2tf32(src[12]) };
    reinterpret_cast<uint4*>(g_xp)[i] = o;
}

// W [K][N] fp32 -> [N][K] tf32 permuted (transpose). MODE 0: Wqkv, MODE 1: Wproj.
template <int MODE>
__global__ void transB(const float* __restrict__ W)
{
    uint32_t* __restrict__ out = MODE ? g_wprojp : g_wqkvp;
    const int N = MODE ? CD : CNQKV;
    __shared__ float tile[32][33];
    const int tx = threadIdx.x, ty = threadIdx.y;
    const int nb = blockIdx.x, kb = blockIdx.y;
    #pragma unroll
    for (int r = 0; r < 4; r++) {
        const int kl = ty + 8 * r;
        tile[kl][tx] = W[(size_t)(kb * 32 + kl) * N + nb * 32 + tx];
    }
    __syncthreads();
    const int ksrc = ((tx & 7) << 2) + (tx >> 3);   // inverse perm
    #pragma unroll
    for (int r = 0; r < 4; r++) {
        const int nl = ty + 8 * r;
        out[(size_t)(nb * 32 + nl) * CD + kb * 32 + tx] = f2tf32(tile[ksrc][nl]);
    }
}

// ============================================================================
// tf32 mma.sync GEMM v3: C(256x128) = A @ W^T-stored + bias.
// 3-stage cp.async pipeline, ONE __syncthreads per chunk.
// 8 warps, warp grid 4(m) x 2(n), warp tile 64x64 (4x8 m16n8k8 atoms).
// MODE 0: A=g_xp, B=g_wqkvp, scatter into g_q/g_k/g_v.  MODE 1: A=g_ctxp, B=g_wprojp -> out.
// ============================================================================
template <int MODE>
__global__ void __launch_bounds__(256)
gemm_tc2(const float* __restrict__ bias, float* __restrict__ out, int N)
{
    const uint32_t* __restrict__ Ap = MODE ? g_ctxp : g_xp;
    const uint32_t* __restrict__ Bp = MODE ? g_wprojp : g_wqkvp;
    constexpr int K = CD;

    extern __shared__ uint32_t smu[];
    const uint32_t smbase = smem_u32(smu);

    const int tid  = threadIdx.x;
    const int wid  = tid >> 5;
    const int lane = tid & 31;
    const int g    = lane >> 2;
    const int t    = lane & 3;
    const int wm   = wid & 3;        // 4 m-warps (64 rows each)
    const int wn   = wid >> 2;       // 2 n-warps (64 cols each)
    const int m0   = blockIdx.y * 256;
    const int n0   = blockIdx.x * 128;

    float cf[4][8][4];
    #pragma unroll
    for (int im = 0; im < 4; im++)
        #pragma unroll
        for (int in = 0; in < 8; in++)
            #pragma unroll
            for (int r = 0; r < 4; r++) cf[im][in][r] = 0.f;

    auto issue = [&](int c, int p) {
        const uint32_t abase = smbase + (uint32_t)p * SSTG * 4;
        const uint32_t bbase = abase + 256 * PAW * 4;
        const int k0 = c * 32;
        #pragma unroll
        for (int i = 0; i < 8; i++) {          // A: 256 rows x 8 segs
            const int s = tid + 256 * i;
            const int m = s >> 3, q = s & 7;
            const uint32_t dst = abase + (uint32_t)(m * PAW + q * 4) * 4;
            const uint32_t* src = Ap + (size_t)(m0 + m) * K + k0 + q * 4;
            asm volatile("cp.async.cg.shared.global [%0], [%1], 16;"
                         :: "r"(dst), "l"(src));
        }
        #pragma unroll
        for (int i = 0; i < 4; i++) {          // B: 128 rows x 8 segs
            const int s = tid + 256 * i;
            const int n = s >> 3, q = s & 7;
            const uint32_t dst = bbase + (uint32_t)(n * PAW + q * 4) * 4;
            const uint32_t* src = Bp + (size_t)(n0 + n) * K + k0 + q * 4;
            asm volatile("cp.async.cg.shared.global [%0], [%1], 16;"
                         :: "r"(dst), "l"(src));
        }
        asm volatile("cp.async.commit_group;" ::: "memory");
    };

    const int NCH = K / 32;   // 40
    issue(0, 0);
    issue(1, 1);

    for (int c = 0; c < NCH; c++) {
        const int p = c % NSTAGE;
        if (c + 1 < NCH) {
            asm volatile("cp.async.wait_group 1;" ::: "memory");
        } else {
            asm volatile("cp.async.wait_group 0;" ::: "memory");
        }
        __syncthreads();   // data for chunk c visible; slot (c+2)%3 free to refill

        if (c + 2 < NCH) issue(c + 2, (c + 2) % NSTAGE);

        const uint32_t* As = smu + p * SSTG;
        const uint32_t* Bs = As + 256 * PAW;

        #pragma unroll
        for (int kh = 0; kh < 2; kh++) {
            uint4 a[4][2], b[8];
            #pragma unroll
            for (int im = 0; im < 4; im++) {
                const int row = wm * 64 + im * 16 + g;
                a[im][0] = *reinterpret_cast<const uint4*>(As + row * PAW + t * 8 + kh * 4);
                a[im][1] = *reinterpret_cast<const uint4*>(As + (row + 8) * PAW + t * 8 + kh * 4);
            }
            #pragma unroll
            for (int in = 0; in < 8; in++) {
                const int n = wn * 64 + in * 8 + g;
                b[in] = *reinterpret_cast<const uint4*>(Bs + n * PAW + t * 8 + kh * 4);
            }
            #pragma unroll
            for (int ks2 = 0; ks2 < 2; ks2++) {
                #pragma unroll
                for (int im = 0; im < 4; im++) {
                    const uint32_t a0 = ks2 ? a[im][0].z : a[im][0].x;
                    const uint32_t a2 = ks2 ? a[im][0].w : a[im][0].y;
                    const uint32_t a1 = ks2 ? a[im][1].z : a[im][1].x;
                    const uint32_t a3 = ks2 ? a[im][1].w : a[im][1].y;
                    #pragma unroll
                    for (int in = 0; in < 8; in++) {
                        const uint32_t b0 = ks2 ? b[in].z : b[in].x;
                        const uint32_t b1 = ks2 ? b[in].w : b[in].y;
                        mma_tf32(cf[im][in], a0, a1, a2, a3, b0, b1);
                    }
                }
            }
        }
    }
    __syncthreads();

    // ---- epilogue: +bias, float2 stores ----
    #pragma unroll
    for (int im = 0; im < 4; im++) {
        #pragma unroll
        for (int in = 0; in < 8; in++) {
            const int mrow0 = m0 + wm * 64 + im * 16 + g;
            const int ncol  = n0 + wn * 64 + in * 8 + 2 * t;
            const float2 bb = *reinterpret_cast<const float2*>(bias + ncol);
            #pragma unroll
            for (int h2 = 0; h2 < 2; h2++) {
                const int m = mrow0 + h2 * 8;
                float2 v;
                v.x = cf[im][in][h2 * 2 + 0] + bb.x;
                v.y = cf[im][in][h2 * 2 + 1] + bb.y;
                if (MODE == 0) {
                    const int b = m >> 10;
                    const int s = m & 1023;
                    const int which = ncol / CD;        // 0=q 1=k 2=v
                    const int r = ncol - which * CD;
                    const int h = r / CHD;
                    const int d = r - h * CHD;
                    const size_t di = ((size_t)(b * CH + h) * CS + s) * CHD + d;
                    float* dst = (which == 0) ? g_q : (which == 1) ? g_k : g_v;
                    *reinterpret_cast<float2*>(dst + di) = v;
                } else {
                    *reinterpret_cast<float2*>(out + (size_t)m * CD + ncol) = v;
                }
            }
        }
    }
}

// ============================================================================
// RoPE (half-rotation), unchanged.
// ============================================================================
__global__ void __launch_bounds__(256)
rope_kernel(const float* __restrict__ cosb, const float* __restrict__ sinb)
{
    const int idx = blockIdx.x * blockDim.x + threadIdx.x;
    constexpr int TOT = CB * CH * CS * (CHD / 2);
    if (idx >= TOT) return;
    const int d  = idx % (CHD / 2);
    const int s  = (idx / (CHD / 2)) % CS;
    const int bh = idx / ((CHD / 2) * CS);

    const float c  = cosb[s * CHD + d];
    const float sn = sinb[s * CHD + d];
    const size_t base = ((size_t)bh * CS + s) * CHD;

    float q1 = g_q[base + d], q2 = g_q[base + d + 40];
    g_q[base + d]      = q1 * c - q2 * sn;
    g_q[base + d + 40] = q2 * c + q1 * sn;

    float k1 = g_k[base + d], k2 = g_k[base + d + 40];
    g_k[base + d]      = k1 * c - k2 * sn;
    g_k[base + d + 40] = k2 * c + k1 * sn;
}

// ============================================================================
// Fused flash attention, tf32 mma.sync. Epilogue writes g_ctxp directly
// (tf32, k-permuted) — permA<1> eliminated.
// ============================================================================
__global__ void __launch_bounds__(256)
attn_tc()
{
    extern __shared__ uint32_t smu[];
    uint32_t* Qs = smu;
    uint32_t* Kt = Qs + 64 * PQ;
    uint32_t* Vs = Kt + 80 * PK;
    float*    Ps = (float*)(Vs + 64 * PV);
    float*    sAlpha = Ps + 64 * PP;
    float*    sL     = sAlpha + 64;

    const int tid  = threadIdx.x;
    const int wid  = tid >> 5;
    const int lane = tid & 31;
    const int g    = lane >> 2;
    const int t    = lane & 3;
    const int wm   = wid & 1;
    const int wn   = wid >> 1;
    const int wq   = wid & 3;
    const int wd   = wid >> 2;
    const int srow = tid >> 2;
    const int sseg = tid & 3;

    const int bh = blockIdx.y;
    const int q0 = blockIdx.x * 64;

    const float* __restrict__ Qg = g_q + (size_t)bh * CS * CHD;
    const float* __restrict__ Kg = g_k + (size_t)bh * CS * CHD;
    const float* __restrict__ Vg = g_v + (size_t)bh * CS * CHD;

    for (int p = tid; p < 64 * CHD; p += 256) {
        const int r = p / CHD, c = p - r * CHD;
        Qs[r * PQ + c] = f2tf32(Qg[(size_t)(q0 + r) * CHD + c] * ATTN_SCALE);
    }

    float m_ = -1e30f, l_ = 0.f;
    float of[5][4];
    #pragma unroll
    for (int i = 0; i < 5; i++)
        #pragma unroll
        for (int r = 0; r < 4; r++) of[i][r] = 0.f;

    for (int tt = 0; tt < CS; tt += 64) {
        __syncthreads();
        for (int p = tid; p < 64 * CHD; p += 256) {
            const int r = p / CHD, c = p - r * CHD;
            Kt[c * PK + r] = f2tf32(Kg[(size_t)(tt + r) * CHD + c]);
            Vs[r * PV + c] = f2tf32(Vg[(size_t)(tt + r) * CHD + c]);
        }
        __syncthreads();

        float sacc[2][2][4];
        #pragma unroll
        for (int im = 0; im < 2; im++)
            #pragma unroll
            for (int in = 0; in < 2; in++)
                #pragma unroll
                for (int r = 0; r < 4; r++) sacc[im][in][r] = 0.f;

        #pragma unroll
        for (int ks = 0; ks < 10; ks++) {
            uint32_t af[2][4], bf[2][2];
            #pragma unroll
            for (int im = 0; im < 2; im++) {
                const int row = wm * 32 + im * 16 + g;
                const int col = ks * 8 + t;
                af[im][0] = Qs[row * PQ + col];
                af[im][1] = Qs[(row + 8) * PQ + col];
                af[im][2] = Qs[row * PQ + col + 4];
                af[im][3] = Qs[(row + 8) * PQ + col + 4];
            }
            #pragma unroll
            for (int in = 0; in < 2; in++) {
                const int n = wn * 16 + in * 8 + g;
                bf[in][0] = Kt[(ks * 8 + t) * PK + n];
                bf[in][1] = Kt[(ks * 8 + t + 4) * PK + n];
            }
            #pragma unroll
            for (int im = 0; im < 2; im++)
                #pragma unroll
                for (int in = 0; in < 2; in++)
                    mma_tf32(sacc[im][in], af[im][0], af[im][1], af[im][2], af[im][3],
                             bf[in][0], bf[in][1]);
        }
        #pragma unroll
        for (int im = 0; im < 2; im++) {
            const int r0 = wm * 32 + im * 16;
            #pragma unroll
            for (int in = 0; in < 2; in++) {
                const int cl = wn * 16 + in * 8 + 2 * t;
                *reinterpret_cast<float2*>(&Ps[(r0 + g) * PP + cl]) =
                    make_float2(sacc[im][in][0], sacc[im][in][1]);
                *reinterpret_cast<float2*>(&Ps[(r0 + g + 8) * PP + cl]) =
                    make_float2(sacc[im][in][2], sacc[im][in][3]);
            }
        }
        __syncthreads();

        {
            float* prow = Ps + srow * PP + sseg * 16;
            float vals[16];
            float mx = -1e30f;
            #pragma unroll
            for (int j = 0; j < 16; j++) { vals[j] = prow[j]; mx = fmaxf(mx, vals[j]); }
            mx = fmaxf(mx, __shfl_xor_sync(0xffffffffu, mx, 1));
            mx = fmaxf(mx, __shfl_xor_sync(0xffffffffu, mx, 2));
            const float mnew  = fmaxf(m_, mx);
            const float alpha = __expf(m_ - mnew);
            float rs = 0.f;
            uint32_t* prow_u = reinterpret_cast<uint32_t*>(prow);
            #pragma unroll
            for (int j = 0; j < 16; j++) {
                const float pj = __expf(vals[j] - mnew);
                rs += pj;
                prow_u[j] = f2tf32(pj);
            }
            rs += __shfl_xor_sync(0xffffffffu, rs, 1);
            rs += __shfl_xor_sync(0xffffffffu, rs, 2);
            l_ = l_ * alpha + rs;
            m_ = mnew;
            if (sseg == 0) sAlpha[srow] = alpha;
        }
        __syncthreads();

        {
            const float aL = sAlpha[wq * 16 + g];
            const float aH = sAlpha[wq * 16 + g + 8];
            #pragma unroll
            for (int in = 0; in < 5; in++) {
                of[in][0] *= aL; of[in][1] *= aL;
                of[in][2] *= aH; of[in][3] *= aH;
            }
            const uint32_t* Pu = reinterpret_cast<const uint32_t*>(Ps);
            #pragma unroll
            for (int ks = 0; ks < 8; ks++) {
                const int row = wq * 16 + g;
                const int col = ks * 8 + t;
                uint32_t a0 = Pu[row * PP + col];
                uint32_t a1 = Pu[(row + 8) * PP + col];
                uint32_t a2 = Pu[row * PP + col + 4];
                uint32_t a3 = Pu[(row + 8) * PP + col + 4];
                #pragma unroll
                for (int in = 0; in < 5; in++) {
                    const int n = wd * 40 + in * 8 + g;
                    const uint32_t b0 = Vs[(ks * 8 + t) * PV + n];
                    const uint32_t b1 = Vs[(ks * 8 + t + 4) * PV + n];
                    mma_tf32(of[in], a0, a1, a2, a3, b0, b1);
                }
            }
        }
    }

    __syncthreads();
    if (sseg == 0) sL[srow] = l_;
    __syncthreads();

    const int b = bh >> 4, h = bh & 15;
    const float invL = 1.f / sL[wq * 16 + g];
    const float invH = 1.f / sL[wq * 16 + g + 8];
    const int rL = q0 + wq * 16 + g;
    const int rH = rL + 8;
    uint32_t* ctxL = g_ctxp + ((size_t)b * CS + rL) * CD;
    uint32_t* ctxH = g_ctxp + ((size_t)b * CS + rH) * CD;
    #pragma unroll
    for (int in = 0; in < 5; in++) {
        const int k0g = h * CHD + wd * 40 + in * 8 + 2 * t;   // even global col
        const int i0 = kperm(k0g);
        const int i1 = kperm(k0g + 1);
        ctxL[i0] = f2tf32(of[in][0] * invL);
        ctxL[i1] = f2tf32(of[in][1] * invL);
        ctxH[i0] = f2tf32(of[in][2] * invH);
        ctxH[i1] = f2tf32(of[in][3] * invH);
    }
}

// ============================================================================
// launch
// ============================================================================
extern "C" void kernel_launch(void* const* d_in, const int* in_sizes, int n_in,
                              void* d_out, int out_size)
{
    const float* x        = (const float*)d_in[0];
    const float* rope_cos = (const float*)d_in[1];
    const float* rope_sin = (const float*)d_in[2];
    const float* Wqkv     = (const float*)d_in[3];
    const float* bqkv     = (const float*)d_in[4];
    const float* Wproj    = (const float*)d_in[5];
    const float* bproj    = (const float*)d_in[6];
    float* out            = (float*)d_out;

    // 0) pre-convert / permute operands to tf32
    permA0<<<CM * CD / 4 / 256, 256>>>(x);
    transB<0><<<dim3(CNQKV / 32, CD / 32), dim3(32, 8)>>>(Wqkv);
    transB<1><<<dim3(CD / 32, CD / 32), dim3(32, 8)>>>(Wproj);

    // 1) QKV projection -> g_q/g_k/g_v
    cudaFuncSetAttribute(gemm_tc2<0>, cudaFuncAttributeMaxDynamicSharedMemorySize, GEMM_SMEM);
    gemm_tc2<0><<<dim3(CNQKV / 128, CM / 256), 256, GEMM_SMEM>>>(bqkv, nullptr, CNQKV);

    // 2) RoPE on q,k
    {
        const int pairs = CB * CH * CS * (CHD / 2);
        rope_kernel<<<(pairs + 255) / 256, 256>>>(rope_cos, rope_sin);
    }

    // 3) fused flash attention -> g_ctxp (tf32, permuted)
    cudaFuncSetAttribute(attn_tc, cudaFuncAttributeMaxDynamicSharedMemorySize, ATTN_SMEM);
    attn_tc<<<dim3(CS / 64, CB * CH), 256, ATTN_SMEM>>>();

    // 4) output projection -> d_out
    cudaFuncSetAttribute(gemm_tc2<1>, cudaFuncAttributeMaxDynamicSharedMemorySize, GEMM_SMEM);
    gemm_tc2<1><<<dim3(CD / 128, CM / 256), 256, GEMM_SMEM>>>(bproj, out, CD);
}

// round 8
// speedup vs baseline: 1.0113x; 1.0022x over previous
#include <cuda_runtime.h>
#include <cstdint>

// ---------------- problem constants ----------------
namespace {
constexpr int CB  = 4;      // batch
constexpr int CS  = 1024;   // seq
constexpr int CD  = 1280;   // model dim
constexpr int CH  = 16;     // heads
constexpr int CHD = 80;     // head dim
constexpr int CM  = CB * CS;          // 4096 rows
constexpr int CNQKV = 3 * CD;         // 3840

// dense GEMM tiling (CTA 256x128, 8 warps, warp tile 64x64), 3-stage cp.async
constexpr int PAW = 36;                       // smem pitch (u32) per 32-k row
constexpr int SSTG = 256 * PAW + 128 * PAW;   // stage stride in u32 = 13824
constexpr int NSTAGE = 3;
constexpr int GEMM_SMEM = NSTAGE * SSTG * 4;  // 165,888 B

// attention smem pitches (u32 units)
constexpr int PQ = 84;
constexpr int PK = 72;
constexpr int PV = 88;
constexpr int PP = 68;
constexpr int ATTN_U32 = 64*PQ + 80*PK + 64*PV + 64*PP + 128;
constexpr int ATTN_SMEM = ATTN_U32 * 4;   // 84,992 B
}
#define ATTN_SCALE 0.11180339887498948f  // 80^-0.5

// ---------------- scratch (device globals; no allocs allowed) ----------------
__device__ __align__(16) float g_q[CB * CH * CS * CHD];     // [b,h,s,d]
__device__ __align__(16) float g_k[CB * CH * CS * CHD];
__device__ __align__(16) float g_v[CB * CH * CS * CHD];
// tf32 pre-converted, k-permuted operands
__device__ __align__(16) uint32_t g_xp[CM * CD];            // [m][k']
__device__ __align__(16) uint32_t g_ctxp[CM * CD];          // [m][k'] (written by attn)
__device__ __align__(16) uint32_t g_wqkvp[CNQKV * CD];      // [n][k']  (transposed)
__device__ __align__(16) uint32_t g_wprojp[CD * CD];        // [n][k']

// ---------------- tf32 helpers ----------------
__device__ __forceinline__ uint32_t f2tf32(float f) {
    uint32_t u;
    asm("cvt.rna.tf32.f32 %0, %1;" : "=r"(u) : "f"(f));
    return u;
}
__device__ __forceinline__ void mma_tf32(float c[4],
                                         uint32_t a0, uint32_t a1, uint32_t a2, uint32_t a3,
                                         uint32_t b0, uint32_t b1) {
    asm volatile(
        "mma.sync.aligned.m16n8k8.row.col.f32.tf32.tf32.f32 "
        "{%0,%1,%2,%3}, {%4,%5,%6,%7}, {%8,%9}, {%0,%1,%2,%3};"
        : "+f"(c[0]), "+f"(c[1]), "+f"(c[2]), "+f"(c[3])
        : "r"(a0), "r"(a1), "r"(a2), "r"(a3), "r"(b0), "r"(b1));
}
__device__ __forceinline__ uint32_t smem_u32(const void* p) {
    uint32_t a;
    asm("{ .reg .u64 t; cvta.to.shared.u64 t, %1; cvt.u32.u64 %0, t; }"
        : "=r"(a) : "l"(p));
    return a;
}
// k-permutation within each 32-block: k' = (k%4)*8 + k/4
__device__ __forceinline__ int kperm(int k) {
    const int kb = k >> 5, kl = k & 31;
    return kb * 32 + (kl & 3) * 8 + (kl >> 2);
}

// ============================================================================
// Pre-convert kernels (x and weights only; ctx is produced permuted by attn).
// ============================================================================
__global__ void __launch_bounds__(256)
permA0(const float* __restrict__ in)
{
    const int i = blockIdx.x * 256 + threadIdx.x;      // output float4 index
    const int m  = i / (CD / 4);
    const int c4 = i - m * (CD / 4);
    const int kb = c4 >> 3, q = c4 & 7;
    const float* src = in + (size_t)m * CD + kb * 32 + 16 * (q & 1) + (q >> 1);
    uint4 o = { f2tf32(src[0]), f2tf32(src[4]), f2tf32(src[8]), f2tf32(src[12]) };
    reinterpret_cast<uint4*>(g_xp)[i] = o;
}

// W [K][N] fp32 -> [N][K] tf32 permuted (transpose). MODE 0: Wqkv, MODE 1: Wproj.
template <int MODE>
__global__ void transB(const float* __restrict__ W)
{
    uint32_t* __restrict__ out = MODE ? g_wprojp : g_wqkvp;
    const int N = MODE ? CD : CNQKV;
    __shared__ float tile[32][33];
    const int tx = threadIdx.x, ty = threadIdx.y;
    const int nb = blockIdx.x, kb = blockIdx.y;
    #pragma unroll
    for (int r = 0; r < 4; r++) {
        const int kl = ty + 8 * r;
        tile[kl][tx] = W[(size_t)(kb * 32 + kl) * N + nb * 32 + tx];
    }
    __syncthreads();
    const int ksrc = ((tx & 7) << 2) + (tx >> 3);   // inverse perm
    #pragma unroll
    for (int r = 0; r < 4; r++) {
        const int nl = ty + 8 * r;
        out[(size_t)(nb * 32 + nl) * CD + kb * 32 + tx] = f2tf32(tile[ksrc][nl]);
    }
}

// ============================================================================
// tf32 mma.sync GEMM v3: C(256x128) = A @ W^T-stored + bias.
// 3-stage cp.async pipeline, ONE __syncthreads per chunk.
// 8 warps, warp grid 4(m) x 2(n), warp tile 64x64 (4x8 m16n8k8 atoms).
// MODE 0: A=g_xp, B=g_wqkvp, scatter into g_q/g_k/g_v.  MODE 1: A=g_ctxp, B=g_wprojp -> out.
// ============================================================================
template <int MODE>
__global__ void __launch_bounds__(256)
gemm_tc2(const float* __restrict__ bias, float* __restrict__ out, int N)
{
    const uint32_t* __restrict__ Ap = MODE ? g_ctxp : g_xp;
    const uint32_t* __restrict__ Bp = MODE ? g_wprojp : g_wqkvp;
    constexpr int K = CD;

    extern __shared__ uint32_t smu[];
    const uint32_t smbase = smem_u32(smu);

    const int tid  = threadIdx.x;
    const int wid  = tid >> 5;
    const int lane = tid & 31;
    const int g    = lane >> 2;
    const int t    = lane & 3;
    const int wm   = wid & 3;        // 4 m-warps (64 rows each)
    const int wn   = wid >> 2;       // 2 n-warps (64 cols each)
    const int m0   = blockIdx.y * 256;
    const int n0   = blockIdx.x * 128;

    float cf[4][8][4];
    #pragma unroll
    for (int im = 0; im < 4; im++)
        #pragma unroll
        for (int in = 0; in < 8; in++)
            #pragma unroll
            for (int r = 0; r < 4; r++) cf[im][in][r] = 0.f;

    auto issue = [&](int c, int p) {
        const uint32_t abase = smbase + (uint32_t)p * SSTG * 4;
        const uint32_t bbase = abase + 256 * PAW * 4;
        const int k0 = c * 32;
        #pragma unroll
        for (int i = 0; i < 8; i++) {          // A: 256 rows x 8 segs
            const int s = tid + 256 * i;
            const int m = s >> 3, q = s & 7;
            const uint32_t dst = abase + (uint32_t)(m * PAW + q * 4) * 4;
            const uint32_t* src = Ap + (size_t)(m0 + m) * K + k0 + q * 4;
            asm volatile("cp.async.cg.shared.global [%0], [%1], 16;"
                         :: "r"(dst), "l"(src));
        }
        #pragma unroll
        for (int i = 0; i < 4; i++) {          // B: 128 rows x 8 segs
            const int s = tid + 256 * i;
            const int n = s >> 3, q = s & 7;
            const uint32_t dst = bbase + (uint32_t)(n * PAW + q * 4) * 4;
            const uint32_t* src = Bp + (size_t)(n0 + n) * K + k0 + q * 4;
            asm volatile("cp.async.cg.shared.global [%0], [%1], 16;"
                         :: "r"(dst), "l"(src));
        }
        asm volatile("cp.async.commit_group;" ::: "memory");
    };

    const int NCH = K / 32;   // 40
    issue(0, 0);
    issue(1, 1);

    for (int c = 0; c < NCH; c++) {
        const int p = c % NSTAGE;
        if (c + 1 < NCH) {
            asm volatile("cp.async.wait_group 1;" ::: "memory");
        } else {
            asm volatile("cp.async.wait_group 0;" ::: "memory");
        }
        __syncthreads();   // data for chunk c visible; slot (c+2)%3 free to refill

        if (c + 2 < NCH) issue(c + 2, (c + 2) % NSTAGE);

        const uint32_t* As = smu + p * SSTG;
        const uint32_t* Bs = As + 256 * PAW;

        #pragma unroll
        for (int kh = 0; kh < 2; kh++) {
            uint4 a[4][2], b[8];
            #pragma unroll
            for (int im = 0; im < 4; im++) {
                const int row = wm * 64 + im * 16 + g;
                a[im][0] = *reinterpret_cast<const uint4*>(As + row * PAW + t * 8 + kh * 4);
                a[im][1] = *reinterpret_cast<const uint4*>(As + (row + 8) * PAW + t * 8 + kh * 4);
            }
            #pragma unroll
            for (int in = 0; in < 8; in++) {
                const int n = wn * 64 + in * 8 + g;
                b[in] = *reinterpret_cast<const uint4*>(Bs + n * PAW + t * 8 + kh * 4);
            }
            #pragma unroll
            for (int ks2 = 0; ks2 < 2; ks2++) {
                #pragma unroll
                for (int im = 0; im < 4; im++) {
                    const uint32_t a0 = ks2 ? a[im][0].z : a[im][0].x;
                    const uint32_t a2 = ks2 ? a[im][0].w : a[im][0].y;
                    const uint32_t a1 = ks2 ? a[im][1].z : a[im][1].x;
                    const uint32_t a3 = ks2 ? a[im][1].w : a[im][1].y;
                    #pragma unroll
                    for (int in = 0; in < 8; in++) {
                        const uint32_t b0 = ks2 ? b[in].z : b[in].x;
                        const uint32_t b1 = ks2 ? b[in].w : b[in].y;
                        mma_tf32(cf[im][in], a0, a1, a2, a3, b0, b1);
                    }
                }
            }
        }
    }
    __syncthreads();

    // ---- epilogue: +bias, float2 stores ----
    #pragma unroll
    for (int im = 0; im < 4; im++) {
        #pragma unroll
        for (int in = 0; in < 8; in++) {
            const int mrow0 = m0 + wm * 64 + im * 16 + g;
            const int ncol  = n0 + wn * 64 + in * 8 + 2 * t;
            const float2 bb = *reinterpret_cast<const float2*>(bias + ncol);
            #pragma unroll
            for (int h2 = 0; h2 < 2; h2++) {
                const int m = mrow0 + h2 * 8;
                float2 v;
                v.x = cf[im][in][h2 * 2 + 0] + bb.x;
                v.y = cf[im][in][h2 * 2 + 1] + bb.y;
                if (MODE == 0) {
                    const int b = m >> 10;
                    const int s = m & 1023;
                    const int which = ncol / CD;        // 0=q 1=k 2=v
                    const int r = ncol - which * CD;
                    const int h = r / CHD;
                    const int d = r - h * CHD;
                    const size_t di = ((size_t)(b * CH + h) * CS + s) * CHD + d;
                    float* dst = (which == 0) ? g_q : (which == 1) ? g_k : g_v;
                    *reinterpret_cast<float2*>(dst + di) = v;
                } else {
                    *reinterpret_cast<float2*>(out + (size_t)m * CD + ncol) = v;
                }
            }
        }
    }
}

// ============================================================================
// RoPE (half-rotation), unchanged.
// ============================================================================
__global__ void __launch_bounds__(256)
rope_kernel(const float* __restrict__ cosb, const float* __restrict__ sinb)
{
    const int idx = blockIdx.x * blockDim.x + threadIdx.x;
    constexpr int TOT = CB * CH * CS * (CHD / 2);
    if (idx >= TOT) return;
    const int d  = idx % (CHD / 2);
    const int s  = (idx / (CHD / 2)) % CS;
    const int bh = idx / ((CHD / 2) * CS);

    const float c  = cosb[s * CHD + d];
    const float sn = sinb[s * CHD + d];
    const size_t base = ((size_t)bh * CS + s) * CHD;

    float q1 = g_q[base + d], q2 = g_q[base + d + 40];
    g_q[base + d]      = q1 * c - q2 * sn;
    g_q[base + d + 40] = q2 * c + q1 * sn;

    float k1 = g_k[base + d], k2 = g_k[base + d + 40];
    g_k[base + d]      = k1 * c - k2 * sn;
    g_k[base + d + 40] = k2 * c + k1 * sn;
}

// ============================================================================
// Fused flash attention, tf32 mma.sync. Epilogue writes g_ctxp directly
// (tf32, k-permuted) — permA<1> eliminated.
// ============================================================================
__global__ void __launch_bounds__(256)
attn_tc()
{
    extern __shared__ uint32_t smu[];
    uint32_t* Qs = smu;
    uint32_t* Kt = Qs + 64 * PQ;
    uint32_t* Vs = Kt + 80 * PK;
    float*    Ps = (float*)(Vs + 64 * PV);
    float*    sAlpha = Ps + 64 * PP;
    float*    sL     = sAlpha + 64;

    const int tid  = threadIdx.x;
    const int wid  = tid >> 5;
    const int lane = tid & 31;
    const int g    = lane >> 2;
    const int t    = lane & 3;
    const int wm   = wid & 1;
    const int wn   = wid >> 1;
    const int wq   = wid & 3;
    const int wd   = wid >> 2;
    const int srow = tid >> 2;
    const int sseg = tid & 3;

    const int bh = blockIdx.y;
    const int q0 = blockIdx.x * 64;

    const float* __restrict__ Qg = g_q + (size_t)bh * CS * CHD;
    const float* __restrict__ Kg = g_k + (size_t)bh * CS * CHD;
    const float* __restrict__ Vg = g_v + (size_t)bh * CS * CHD;

    for (int p = tid; p < 64 * CHD; p += 256) {
        const int r = p / CHD, c = p - r * CHD;
        Qs[r * PQ + c] = f2tf32(Qg[(size_t)(q0 + r) * CHD + c] * ATTN_SCALE);
    }

    float m_ = -1e30f, l_ = 0.f;
    float of[5][4];
    #pragma unroll
    for (int i = 0; i < 5; i++)
        #pragma unroll
        for (int r = 0; r < 4; r++) of[i][r] = 0.f;

    for (int tt = 0; tt < CS; tt += 64) {
        __syncthreads();
        for (int p = tid; p < 64 * CHD; p += 256) {
            const int r = p / CHD, c = p - r * CHD;
            Kt[c * PK + r] = f2tf32(Kg[(size_t)(tt + r) * CHD + c]);
            Vs[r * PV + c] = f2tf32(Vg[(size_t)(tt + r) * CHD + c]);
        }
        __syncthreads();

        float sacc[2][2][4];
        #pragma unroll
        for (int im = 0; im < 2; im++)
            #pragma unroll
            for (int in = 0; in < 2; in++)
                #pragma unroll
                for (int r = 0; r < 4; r++) sacc[im][in][r] = 0.f;

        #pragma unroll
        for (int ks = 0; ks < 10; ks++) {
            uint32_t af[2][4], bf[2][2];
            #pragma unroll
            for (int im = 0; im < 2; im++) {
                const int row = wm * 32 + im * 16 + g;
                const int col = ks * 8 + t;
                af[im][0] = Qs[row * PQ + col];
                af[im][1] = Qs[(row + 8) * PQ + col];
                af[im][2] = Qs[row * PQ + col + 4];
                af[im][3] = Qs[(row + 8) * PQ + col + 4];
            }
            #pragma unroll
            for (int in = 0; in < 2; in++) {
                const int n = wn * 16 + in * 8 + g;
                bf[in][0] = Kt[(ks * 8 + t) * PK + n];
                bf[in][1] = Kt[(ks * 8 + t + 4) * PK + n];
            }
            #pragma unroll
            for (int im = 0; im < 2; im++)
                #pragma unroll
                for (int in = 0; in < 2; in++)
                    mma_tf32(sacc[im][in], af[im][0], af[im][1], af[im][2], af[im][3],
                             bf[in][0], bf[in][1]);
        }
        #pragma unroll
        for (int im = 0; im < 2; im++) {
            const int r0 = wm * 32 + im * 16;
            #pragma unroll
            for (int in = 0; in < 2; in++) {
                const int cl = wn * 16 + in * 8 + 2 * t;
                *reinterpret_cast<float2*>(&Ps[(r0 + g) * PP + cl]) =
                    make_float2(sacc[im][in][0], sacc[im][in][1]);
                *reinterpret_cast<float2*>(&Ps[(r0 + g + 8) * PP + cl]) =
                    make_float2(sacc[im][in][2], sacc[im][in][3]);
            }
        }
        __syncthreads();

        {
            float* prow = Ps + srow * PP + sseg * 16;
            float vals[16];
            float mx = -1e30f;
            #pragma unroll
            for (int j = 0; j < 16; j++) { vals[j] = prow[j]; mx = fmaxf(mx, vals[j]); }
            mx = fmaxf(mx, __shfl_xor_sync(0xffffffffu, mx, 1));
            mx = fmaxf(mx, __shfl_xor_sync(0xffffffffu, mx, 2));
            const float mnew  = fmaxf(m_, mx);
            const float alpha = __expf(m_ - mnew);
            float rs = 0.f;
            uint32_t* prow_u = reinterpret_cast<uint32_t*>(prow);
            #pragma unroll
            for (int j = 0; j < 16; j++) {
                const float pj = __expf(vals[j] - mnew);
                rs += pj;
                prow_u[j] = f2tf32(pj);
            }
            rs += __shfl_xor_sync(0xffffffffu, rs, 1);
            rs += __shfl_xor_sync(0xffffffffu, rs, 2);
            l_ = l_ * alpha + rs;
            m_ = mnew;
            if (sseg == 0) sAlpha[srow] = alpha;
        }
        __syncthreads();

        {
            const float aL = sAlpha[wq * 16 + g];
            const float aH = sAlpha[wq * 16 + g + 8];
            #pragma unroll
            for (int in = 0; in < 5; in++) {
                of[in][0] *= aL; of[in][1] *= aL;
                of[in][2] *= aH; of[in][3] *= aH;
            }
            const uint32_t* Pu = reinterpret_cast<const uint32_t*>(Ps);
            #pragma unroll
            for (int ks = 0; ks < 8; ks++) {
                const int row = wq * 16 + g;
                const int col = ks * 8 + t;
                uint32_t a0 = Pu[row * PP + col];
                uint32_t a1 = Pu[(row + 8) * PP + col];
                uint32_t a2 = Pu[row * PP + col + 4];
                uint32_t a3 = Pu[(row + 8) * PP + col + 4];
                #pragma unroll
                for (int in = 0; in < 5; in++) {
                    const int n = wd * 40 + in * 8 + g;
                    const uint32_t b0 = Vs[(ks * 8 + t) * PV + n];
                    const uint32_t b1 = Vs[(ks * 8 + t + 4) * PV + n];
                    mma_tf32(of[in], a0, a1, a2, a3, b0, b1);
                }
            }
        }
    }

    __syncthreads();
    if (sseg == 0) sL[srow] = l_;
    __syncthreads();

    const int b = bh >> 4, h = bh & 15;
    const float invL = 1.f / sL[wq * 16 + g];
    const float invH = 1.f / sL[wq * 16 + g + 8];
    const int rL = q0 + wq * 16 + g;
    const int rH = rL + 8;
    uint32_t* ctxL = g_ctxp + ((size_t)b * CS + rL) * CD;
    uint32_t* ctxH = g_ctxp + ((size_t)b * CS + rH) * CD;
    #pragma unroll
    for (int in = 0; in < 5; in++) {
        const int k0g = h * CHD + wd * 40 + in * 8 + 2 * t;   // even global col
        const int i0 = kperm(k0g);
        const int i1 = kperm(k0g + 1);
        ctxL[i0] = f2tf32(of[in][0] * invL);
        ctxL[i1] = f2tf32(of[in][1] * invL);
        ctxH[i0] = f2tf32(of[in][2] * invH);
        ctxH[i1] = f2tf32(of[in][3] * invH);
    }
}

// ============================================================================
// launch
// ============================================================================
extern "C" void kernel_launch(void* const* d_in, const int* in_sizes, int n_in,
                              void* d_out, int out_size)
{
    const float* x        = (const float*)d_in[0];
    const float* rope_cos = (const float*)d_in[1];
    const float* rope_sin = (const float*)d_in[2];
    const float* Wqkv     = (const float*)d_in[3];
    const float* bqkv     = (const float*)d_in[4];
    const float* Wproj    = (const float*)d_in[5];
    const float* bproj    = (const float*)d_in[6];
    float* out            = (float*)d_out;

    // 0) pre-convert / permute operands to tf32
    permA0<<<CM * CD / 4 / 256, 256>>>(x);
    transB<0><<<dim3(CNQKV / 32, CD / 32), dim3(32, 8)>>>(Wqkv);
    transB<1><<<dim3(CD / 32, CD / 32), dim3(32, 8)>>>(Wproj);

    // 1) QKV projection -> g_q/g_k/g_v
    cudaFuncSetAttribute(gemm_tc2<0>, cudaFuncAttributeMaxDynamicSharedMemorySize, GEMM_SMEM);
    gemm_tc2<0><<<dim3(CNQKV / 128, CM / 256), 256, GEMM_SMEM>>>(bqkv, nullptr, CNQKV);

    // 2) RoPE on q,k
    {
        const int pairs = CB * CH * CS * (CHD / 2);
        rope_kernel<<<(pairs + 255) / 256, 256>>>(rope_cos, rope_sin);
    }

    // 3) fused flash attention -> g_ctxp (tf32, permuted)
    cudaFuncSetAttribute(attn_tc, cudaFuncAttributeMaxDynamicSharedMemorySize, ATTN_SMEM);
    attn_tc<<<dim3(CS / 64, CB * CH), 256, ATTN_SMEM>>>();

    // 4) output projection -> d_out
    cudaFuncSetAttribute(gemm_tc2<1>, cudaFuncAttributeMaxDynamicSharedMemorySize, GEMM_SMEM);
    gemm_tc2<1><<<dim3(CD / 128, CM / 256), 256, GEMM_SMEM>>>(bproj, out, CD);
}

// round 9
// speedup vs baseline: 1.1171x; 1.1047x over previous
#include <cuda_runtime.h>
#include <cstdint>

// ---------------- problem constants ----------------
namespace {
constexpr int CB  = 4;      // batch
constexpr int CS  = 1024;   // seq
constexpr int CD  = 1280;   // model dim
constexpr int CH  = 16;     // heads
constexpr int CHD = 80;     // head dim
constexpr int CM  = CB * CS;          // 4096 rows
constexpr int CNQKV = 3 * CD;         // 3840

// dense GEMM tiling (CTA 128x128, 4 warps, warp tile 64x64), 3-stage cp.async
constexpr int PAW = 36;                       // smem pitch (u32) per 32-k row
constexpr int SSTG = 128 * PAW + 128 * PAW;   // stage stride in u32 = 9216
constexpr int NSTAGE = 3;
constexpr int GEMM_SMEM = NSTAGE * SSTG * 4;  // 110,592 B  (x2 CTAs = 216KB <= 228KB)

// attention smem pitches (u32 units)
constexpr int PQ = 84;
constexpr int PK = 72;
constexpr int PV = 88;
constexpr int PP = 68;
constexpr int ATTN_U32 = 64*PQ + 80*PK + 64*PV + 64*PP + 128;
constexpr int ATTN_SMEM = ATTN_U32 * 4;   // 84,992 B
}
#define ATTN_SCALE 0.11180339887498948f  // 80^-0.5

// ---------------- scratch (device globals; no allocs allowed) ----------------
__device__ __align__(16) float g_q[CB * CH * CS * CHD];     // [b,h,s,d]
__device__ __align__(16) float g_k[CB * CH * CS * CHD];
__device__ __align__(16) float g_v[CB * CH * CS * CHD];
// tf32 pre-converted, k-permuted operands
__device__ __align__(16) uint32_t g_xp[CM * CD];            // [m][k']
__device__ __align__(16) uint32_t g_ctxp[CM * CD];          // [m][k'] (written by attn)
__device__ __align__(16) uint32_t g_wqkvp[CNQKV * CD];      // [n][k']  (transposed)
__device__ __align__(16) uint32_t g_wprojp[CD * CD];        // [n][k']

// ---------------- tf32 helpers ----------------
__device__ __forceinline__ uint32_t f2tf32(float f) {
    uint32_t u;
    asm("cvt.rna.tf32.f32 %0, %1;" : "=r"(u) : "f"(f));
    return u;
}
__device__ __forceinline__ void mma_tf32(float c[4],
                                         uint32_t a0, uint32_t a1, uint32_t a2, uint32_t a3,
                                         uint32_t b0, uint32_t b1) {
    asm volatile(
        "mma.sync.aligned.m16n8k8.row.col.f32.tf32.tf32.f32 "
        "{%0,%1,%2,%3}, {%4,%5,%6,%7}, {%8,%9}, {%0,%1,%2,%3};"
        : "+f"(c[0]), "+f"(c[1]), "+f"(c[2]), "+f"(c[3])
        : "r"(a0), "r"(a1), "r"(a2), "r"(a3), "r"(b0), "r"(b1));
}
__device__ __forceinline__ uint32_t smem_u32(const void* p) {
    uint32_t a;
    asm("{ .reg .u64 t; cvta.to.shared.u64 t, %1; cvt.u32.u64 %0, t; }"
        : "=r"(a) : "l"(p));
    return a;
}
// k-permutation within each 32-block: k' = (k%4)*8 + k/4
__device__ __forceinline__ int kperm(int k) {
    const int kb = k >> 5, kl = k & 31;
    return kb * 32 + (kl & 3) * 8 + (kl >> 2);
}

// ============================================================================
// Pre-convert kernels (x and weights only; ctx is produced permuted by attn).
// ============================================================================
__global__ void __launch_bounds__(256)
permA0(const float* __restrict__ in)
{
    const int i = blockIdx.x * 256 + threadIdx.x;      // output float4 index
    const int m  = i / (CD / 4);
    const int c4 = i - m * (CD / 4);
    const int kb = c4 >> 3, q = c4 & 7;
    const float* src = in + (size_t)m * CD + kb * 32 + 16 * (q & 1) + (q >> 1);
    uint4 o = { f2tf32(src[0]), f2tf32(src[4]), f2tf32(src[8]), f2tf32(src[12]) };
    reinterpret_cast<uint4*>(g_xp)[i] = o;
}

// W [K][N] fp32 -> [N][K] tf32 permuted (transpose). MODE 0: Wqkv, MODE 1: Wproj.
template <int MODE>
__global__ void transB(const float* __restrict__ W)
{
    uint32_t* __restrict__ out = MODE ? g_wprojp : g_wqkvp;
    const int N = MODE ? CD : CNQKV;
    __shared__ float tile[32][33];
    const int tx = threadIdx.x, ty = threadIdx.y;
    const int nb = blockIdx.x, kb = blockIdx.y;
    #pragma unroll
    for (int r = 0; r < 4; r++) {
        const int kl = ty + 8 * r;
        tile[kl][tx] = W[(size_t)(kb * 32 + kl) * N + nb * 32 + tx];
    }
    __syncthreads();
    const int ksrc = ((tx & 7) << 2) + (tx >> 3);   // inverse perm
    #pragma unroll
    for (int r = 0; r < 4; r++) {
        const int nl = ty + 8 * r;
        out[(size_t)(nb * 32 + nl) * CD + kb * 32 + tx] = f2tf32(tile[ksrc][nl]);
    }
}

// ============================================================================
// tf32 mma.sync GEMM v4: C(128x128) = A @ W^T-stored + bias.
// 128 threads (4 warps, 2x2), warp tile 64x64 -> 2 CTAs/SM guaranteed
// (128 thr x <=255 regs <= 32K regs; 2 x 108KB smem <= 228KB).
// 3-stage cp.async pipeline, one __syncthreads per chunk.
// MODE 0: A=g_xp, B=g_wqkvp, scatter into g_q/g_k/g_v.  MODE 1: A=g_ctxp, B=g_wprojp -> out.
// ============================================================================
template <int MODE>
__global__ void __launch_bounds__(128)
gemm_tc3(const float* __restrict__ bias, float* __restrict__ out, int N)
{
    const uint32_t* __restrict__ Ap = MODE ? g_ctxp : g_xp;
    const uint32_t* __restrict__ Bp = MODE ? g_wprojp : g_wqkvp;
    constexpr int K = CD;

    extern __shared__ uint32_t smu[];
    const uint32_t smbase = smem_u32(smu);

    const int tid  = threadIdx.x;
    const int wid  = tid >> 5;
    const int lane = tid & 31;
    const int g    = lane >> 2;
    const int t    = lane & 3;
    const int wm   = wid & 1;        // 2 m-warps (64 rows each)
    const int wn   = wid >> 1;       // 2 n-warps (64 cols each)
    const int m0   = blockIdx.y * 128;
    const int n0   = blockIdx.x * 128;

    float cf[4][8][4];
    #pragma unroll
    for (int im = 0; im < 4; im++)
        #pragma unroll
        for (int in = 0; in < 8; in++)
            #pragma unroll
            for (int r = 0; r < 4; r++) cf[im][in][r] = 0.f;

    auto issue = [&](int c, int p) {
        const uint32_t abase = smbase + (uint32_t)p * SSTG * 4;
        const uint32_t bbase = abase + 128 * PAW * 4;
        const int k0 = c * 32;
        #pragma unroll
        for (int i = 0; i < 8; i++) {          // A: 128 rows x 8 segs, 128 thr
            const int s = tid + 128 * i;
            const int m = s >> 3, q = s & 7;
            const uint32_t dst = abase + (uint32_t)(m * PAW + q * 4) * 4;
            const uint32_t* src = Ap + (size_t)(m0 + m) * K + k0 + q * 4;
            asm volatile("cp.async.cg.shared.global [%0], [%1], 16;"
                         :: "r"(dst), "l"(src));
        }
        #pragma unroll
        for (int i = 0; i < 8; i++) {          // B: 128 rows x 8 segs
            const int s = tid + 128 * i;
            const int n = s >> 3, q = s & 7;
            const uint32_t dst = bbase + (uint32_t)(n * PAW + q * 4) * 4;
            const uint32_t* src = Bp + (size_t)(n0 + n) * K + k0 + q * 4;
            asm volatile("cp.async.cg.shared.global [%0], [%1], 16;"
                         :: "r"(dst), "l"(src));
        }
        asm volatile("cp.async.commit_group;" ::: "memory");
    };

    const int NCH = K / 32;   // 40
    issue(0, 0);
    issue(1, 1);

    for (int c = 0; c < NCH; c++) {
        const int p = c % NSTAGE;
        if (c + 1 < NCH) {
            asm volatile("cp.async.wait_group 1;" ::: "memory");
        } else {
            asm volatile("cp.async.wait_group 0;" ::: "memory");
        }
        __syncthreads();   // data for chunk c visible; slot (c+2)%3 free to refill

        if (c + 2 < NCH) issue(c + 2, (c + 2) % NSTAGE);

        const uint32_t* As = smu + p * SSTG;
        const uint32_t* Bs = As + 128 * PAW;

        #pragma unroll
        for (int kh = 0; kh < 2; kh++) {
            uint4 a[4][2], b[8];
            #pragma unroll
            for (int im = 0; im < 4; im++) {
                const int row = wm * 64 + im * 16 + g;
                a[im][0] = *reinterpret_cast<const uint4*>(As + row * PAW + t * 8 + kh * 4);
                a[im][1] = *reinterpret_cast<const uint4*>(As + (row + 8) * PAW + t * 8 + kh * 4);
            }
            #pragma unroll
            for (int in = 0; in < 8; in++) {
                const int n = wn * 64 + in * 8 + g;
                b[in] = *reinterpret_cast<const uint4*>(Bs + n * PAW + t * 8 + kh * 4);
            }
            #pragma unroll
            for (int ks2 = 0; ks2 < 2; ks2++) {
                #pragma unroll
                for (int im = 0; im < 4; im++) {
                    const uint32_t a0 = ks2 ? a[im][0].z : a[im][0].x;
                    const uint32_t a2 = ks2 ? a[im][0].w : a[im][0].y;
                    const uint32_t a1 = ks2 ? a[im][1].z : a[im][1].x;
                    const uint32_t a3 = ks2 ? a[im][1].w : a[im][1].y;
                    #pragma unroll
                    for (int in = 0; in < 8; in++) {
                        const uint32_t b0 = ks2 ? b[in].z : b[in].x;
                        const uint32_t b1 = ks2 ? b[in].w : b[in].y;
                        mma_tf32(cf[im][in], a0, a1, a2, a3, b0, b1);
                    }
                }
            }
        }
    }
    __syncthreads();

    // ---- epilogue: +bias, float2 stores ----
    #pragma unroll
    for (int im = 0; im < 4; im++) {
        #pragma unroll
        for (int in = 0; in < 8; in++) {
            const int mrow0 = m0 + wm * 64 + im * 16 + g;
            const int ncol  = n0 + wn * 64 + in * 8 + 2 * t;
            const float2 bb = *reinterpret_cast<const float2*>(bias + ncol);
            #pragma unroll
            for (int h2 = 0; h2 < 2; h2++) {
                const int m = mrow0 + h2 * 8;
                float2 v;
                v.x = cf[im][in][h2 * 2 + 0] + bb.x;
                v.y = cf[im][in][h2 * 2 + 1] + bb.y;
                if (MODE == 0) {
                    const int b = m >> 10;
                    const int s = m & 1023;
                    const int which = ncol / CD;        // 0=q 1=k 2=v
                    const int r = ncol - which * CD;
                    const int h = r / CHD;
                    const int d = r - h * CHD;
                    const size_t di = ((size_t)(b * CH + h) * CS + s) * CHD + d;
                    float* dst = (which == 0) ? g_q : (which == 1) ? g_k : g_v;
                    *reinterpret_cast<float2*>(dst + di) = v;
                } else {
                    *reinterpret_cast<float2*>(out + (size_t)m * CD + ncol) = v;
                }
            }
        }
    }
}

// ============================================================================
// RoPE (half-rotation), unchanged.
// ============================================================================
__global__ void __launch_bounds__(256)
rope_kernel(const float* __restrict__ cosb, const float* __restrict__ sinb)
{
    const int idx = blockIdx.x * blockDim.x + threadIdx.x;
    constexpr int TOT = CB * CH * CS * (CHD / 2);
    if (idx >= TOT) return;
    const int d  = idx % (CHD / 2);
    const int s  = (idx / (CHD / 2)) % CS;
    const int bh = idx / ((CHD / 2) * CS);

    const float c  = cosb[s * CHD + d];
    const float sn = sinb[s * CHD + d];
    const size_t base = ((size_t)bh * CS + s) * CHD;

    float q1 = g_q[base + d], q2 = g_q[base + d + 40];
    g_q[base + d]      = q1 * c - q2 * sn;
    g_q[base + d + 40] = q2 * c + q1 * sn;

    float k1 = g_k[base + d], k2 = g_k[base + d + 40];
    g_k[base + d]      = k1 * c - k2 * sn;
    g_k[base + d + 40] = k2 * c + k1 * sn;
}

// ============================================================================
// Fused flash attention, tf32 mma.sync. Epilogue writes g_ctxp directly
// (tf32, k-permuted).
// ============================================================================
__global__ void __launch_bounds__(256)
attn_tc()
{
    extern __shared__ uint32_t smu[];
    uint32_t* Qs = smu;
    uint32_t* Kt = Qs + 64 * PQ;
    uint32_t* Vs = Kt + 80 * PK;
    float*    Ps = (float*)(Vs + 64 * PV);
    float*    sAlpha = Ps + 64 * PP;
    float*    sL     = sAlpha + 64;

    const int tid  = threadIdx.x;
    const int wid  = tid >> 5;
    const int lane = tid & 31;
    const int g    = lane >> 2;
    const int t    = lane & 3;
    const int wm   = wid & 1;
    const int wn   = wid >> 1;
    const int wq   = wid & 3;
    const int wd   = wid >> 2;
    const int srow = tid >> 2;
    const int sseg = tid & 3;

    const int bh = blockIdx.y;
    const int q0 = blockIdx.x * 64;

    const float* __restrict__ Qg = g_q + (size_t)bh * CS * CHD;
    const float* __restrict__ Kg = g_k + (size_t)bh * CS * CHD;
    const float* __restrict__ Vg = g_v + (size_t)bh * CS * CHD;

    for (int p = tid; p < 64 * CHD; p += 256) {
        const int r = p / CHD, c = p - r * CHD;
        Qs[r * PQ + c] = f2tf32(Qg[(size_t)(q0 + r) * CHD + c] * ATTN_SCALE);
    }

    float m_ = -1e30f, l_ = 0.f;
    float of[5][4];
    #pragma unroll
    for (int i = 0; i < 5; i++)
        #pragma unroll
        for (int r = 0; r < 4; r++) of[i][r] = 0.f;

    for (int tt = 0; tt < CS; tt += 64) {
        __syncthreads();
        for (int p = tid; p < 64 * CHD; p += 256) {
            const int r = p / CHD, c = p - r * CHD;
            Kt[c * PK + r] = f2tf32(Kg[(size_t)(tt + r) * CHD + c]);
            Vs[r * PV + c] = f2tf32(Vg[(size_t)(tt + r) * CHD + c]);
        }
        __syncthreads();

        float sacc[2][2][4];
        #pragma unroll
        for (int im = 0; im < 2; im++)
            #pragma unroll
            for (int in = 0; in < 2; in++)
                #pragma unroll
                for (int r = 0; r < 4; r++) sacc[im][in][r] = 0.f;

        #pragma unroll
        for (int ks = 0; ks < 10; ks++) {
            uint32_t af[2][4], bf[2][2];
            #pragma unroll
            for (int im = 0; im < 2; im++) {
                const int row = wm * 32 + im * 16 + g;
                const int col = ks * 8 + t;
                af[im][0] = Qs[row * PQ + col];
                af[im][1] = Qs[(row + 8) * PQ + col];
                af[im][2] = Qs[row * PQ + col + 4];
                af[im][3] = Qs[(row + 8) * PQ + col + 4];
            }
            #pragma unroll
            for (int in = 0; in < 2; in++) {
                const int n = wn * 16 + in * 8 + g;
                bf[in][0] = Kt[(ks * 8 + t) * PK + n];
                bf[in][1] = Kt[(ks * 8 + t + 4) * PK + n];
            }
            #pragma unroll
            for (int im = 0; im < 2; im++)
                #pragma unroll
                for (int in = 0; in < 2; in++)
                    mma_tf32(sacc[im][in], af[im][0], af[im][1], af[im][2], af[im][3],
                             bf[in][0], bf[in][1]);
        }
        #pragma unroll
        for (int im = 0; im < 2; im++) {
            const int r0 = wm * 32 + im * 16;
            #pragma unroll
            for (int in = 0; in < 2; in++) {
                const int cl = wn * 16 + in * 8 + 2 * t;
                *reinterpret_cast<float2*>(&Ps[(r0 + g) * PP + cl]) =
                    make_float2(sacc[im][in][0], sacc[im][in][1]);
                *reinterpret_cast<float2*>(&Ps[(r0 + g + 8) * PP + cl]) =
                    make_float2(sacc[im][in][2], sacc[im][in][3]);
            }
        }
        __syncthreads();

        {
            float* prow = Ps + srow * PP + sseg * 16;
            float vals[16];
            float mx = -1e30f;
            #pragma unroll
            for (int j = 0; j < 16; j++) { vals[j] = prow[j]; mx = fmaxf(mx, vals[j]); }
            mx = fmaxf(mx, __shfl_xor_sync(0xffffffffu, mx, 1));
            mx = fmaxf(mx, __shfl_xor_sync(0xffffffffu, mx, 2));
            const float mnew  = fmaxf(m_, mx);
            const float alpha = __expf(m_ - mnew);
            float rs = 0.f;
            uint32_t* prow_u = reinterpret_cast<uint32_t*>(prow);
            #pragma unroll
            for (int j = 0; j < 16; j++) {
                const float pj = __expf(vals[j] - mnew);
                rs += pj;
                prow_u[j] = f2tf32(pj);
            }
            rs += __shfl_xor_sync(0xffffffffu, rs, 1);
            rs += __shfl_xor_sync(0xffffffffu, rs, 2);
            l_ = l_ * alpha + rs;
            m_ = mnew;
            if (sseg == 0) sAlpha[srow] = alpha;
        }
        __syncthreads();

        {
            const float aL = sAlpha[wq * 16 + g];
            const float aH = sAlpha[wq * 16 + g + 8];
            #pragma unroll
            for (int in = 0; in < 5; in++) {
                of[in][0] *= aL; of[in][1] *= aL;
                of[in][2] *= aH; of[in][3] *= aH;
            }
            const uint32_t* Pu = reinterpret_cast<const uint32_t*>(Ps);
            #pragma unroll
            for (int ks = 0; ks < 8; ks++) {
                const int row = wq * 16 + g;
                const int col = ks * 8 + t;
                uint32_t a0 = Pu[row * PP + col];
                uint32_t a1 = Pu[(row + 8) * PP + col];
                uint32_t a2 = Pu[row * PP + col + 4];
                uint32_t a3 = Pu[(row + 8) * PP + col + 4];
                #pragma unroll
                for (int in = 0; in < 5; in++) {
                    const int n = wd * 40 + in * 8 + g;
                    const uint32_t b0 = Vs[(ks * 8 + t) * PV + n];
                    const uint32_t b1 = Vs[(ks * 8 + t + 4) * PV + n];
                    mma_tf32(of[in], a0, a1, a2, a3, b0, b1);
                }
            }
        }
    }

    __syncthreads();
    if (sseg == 0) sL[srow] = l_;
    __syncthreads();

    const int b = bh >> 4, h = bh & 15;
    const float invL = 1.f / sL[wq * 16 + g];
    const float invH = 1.f / sL[wq * 16 + g + 8];
    const int rL = q0 + wq * 16 + g;
    const int rH = rL + 8;
    uint32_t* ctxL = g_ctxp + ((size_t)b * CS + rL) * CD;
    uint32_t* ctxH = g_ctxp + ((size_t)b * CS + rH) * CD;
    #pragma unroll
    for (int in = 0; in < 5; in++) {
        const int k0g = h * CHD + wd * 40 + in * 8 + 2 * t;   // even global col
        const int i0 = kperm(k0g);
        const int i1 = kperm(k0g + 1);
        ctxL[i0] = f2tf32(of[in][0] * invL);
        ctxL[i1] = f2tf32(of[in][1] * invL);
        ctxH[i0] = f2tf32(of[in][2] * invH);
        ctxH[i1] = f2tf32(of[in][3] * invH);
    }
}

// ============================================================================
// launch
// ============================================================================
extern "C" void kernel_launch(void* const* d_in, const int* in_sizes, int n_in,
                              void* d_out, int out_size)
{
    const float* x        = (const float*)d_in[0];
    const float* rope_cos = (const float*)d_in[1];
    const float* rope_sin = (const float*)d_in[2];
    const float* Wqkv     = (const float*)d_in[3];
    const float* bqkv     = (const float*)d_in[4];
    const float* Wproj    = (const float*)d_in[5];
    const float* bproj    = (const float*)d_in[6];
    float* out            = (float*)d_out;

    // 0) pre-convert / permute operands to tf32
    permA0<<<CM * CD / 4 / 256, 256>>>(x);
    transB<0><<<dim3(CNQKV / 32, CD / 32), dim3(32, 8)>>>(Wqkv);
    transB<1><<<dim3(CD / 32, CD / 32), dim3(32, 8)>>>(Wproj);

    // 1) QKV projection -> g_q/g_k/g_v
    cudaFuncSetAttribute(gemm_tc3<0>, cudaFuncAttributeMaxDynamicSharedMemorySize, GEMM_SMEM);
    gemm_tc3<0><<<dim3(CNQKV / 128, CM / 128), 128, GEMM_SMEM>>>(bqkv, nullptr, CNQKV);

    // 2) RoPE on q,k
    {
        const int pairs = CB * CH * CS * (CHD / 2);
        rope_kernel<<<(pairs + 255) / 256, 256>>>(rope_cos, rope_sin);
    }

    // 3) fused flash attention -> g_ctxp (tf32, permuted)
    cudaFuncSetAttribute(attn_tc, cudaFuncAttributeMaxDynamicSharedMemorySize, ATTN_SMEM);
    attn_tc<<<dim3(CS / 64, CB * CH), 256, ATTN_SMEM>>>();

    // 4) output projection -> d_out
    cudaFuncSetAttribute(gemm_tc3<1>, cudaFuncAttributeMaxDynamicSharedMemorySize, GEMM_SMEM);
    gemm_tc3<1><<<dim3(CD / 128, CM / 128), 128, GEMM_SMEM>>>(bproj, out, CD);
}

// round 10
// speedup vs baseline: 1.3203x; 1.1818x over previous
#include <cuda_runtime.h>
#include <cstdint>

// ---------------- problem constants ----------------
namespace {
constexpr int CB  = 4;      // batch
constexpr int CS  = 1024;   // seq
constexpr int CD  = 1280;   // model dim
constexpr int CH  = 16;     // heads
constexpr int CHD = 80;     // head dim
constexpr int CM  = CB * CS;          // 4096 rows
constexpr int CNQKV = 3 * CD;         // 3840

// dense GEMM tiling (CTA 128x128, 4 warps, warp tile 64x64), 3-stage cp.async
constexpr int PAW = 36;                       // smem pitch (u32) per 32-k row
constexpr int SSTG = 128 * PAW + 128 * PAW;   // stage stride in u32 = 9216
constexpr int NSTAGE = 3;
constexpr int GEMM_SMEM = NSTAGE * SSTG * 4;  // 110,592 B  (x2 CTAs = 216KB <= 228KB)

// attention smem pitches (u32 units). All row-major now.
constexpr int PQ = 84;   // Qs [64][80]: A-frag bank 20g+t bijective
constexpr int PK2 = 84;  // Ks [64][80]: B-frag bank 20g+t bijective
constexpr int PV = 88;   // Vs [64][80]: B-frag bank 24t+g bijective
constexpr int PP = 68;   // Ps [64][64]: A-frag bank 4g+t bijective
constexpr int ATTN_U32 = 64*PQ + 64*PK2 + 64*PV + 64*PP + 128;  // 20864
constexpr int ATTN_SMEM = ATTN_U32 * 4;   // 83,456 B (x2 = 167KB <= 228KB)
}
#define ATTN_SCALE 0.11180339887498948f  // 80^-0.5

// ---------------- scratch (device globals; no allocs allowed) ----------------
__device__ __align__(16) float    g_q[CB * CH * CS * CHD];    // fp32 (pre-rope)
__device__ __align__(16) float    g_k[CB * CH * CS * CHD];    // fp32 (pre-rope)
__device__ __align__(16) uint32_t g_qp[CB * CH * CS * CHD];   // tf32, roped, *SCALE
__device__ __align__(16) uint32_t g_kp[CB * CH * CS * CHD];   // tf32, roped
__device__ __align__(16) uint32_t g_vp[CB * CH * CS * CHD];   // tf32 (from gemm)
// tf32 pre-converted, k-permuted GEMM operands
__device__ __align__(16) uint32_t g_xp[CM * CD];              // [m][k']
__device__ __align__(16) uint32_t g_ctxp[CM * CD];            // [m][k'] (from attn)
__device__ __align__(16) uint32_t g_wqkvp[CNQKV * CD];        // [n][k'] (transposed)
__device__ __align__(16) uint32_t g_wprojp[CD * CD];          // [n][k']

// ---------------- tf32 helpers ----------------
__device__ __forceinline__ uint32_t f2tf32(float f) {
    uint32_t u;
    asm("cvt.rna.tf32.f32 %0, %1;" : "=r"(u) : "f"(f));
    return u;
}
__device__ __forceinline__ void mma_tf32(float c[4],
                                         uint32_t a0, uint32_t a1, uint32_t a2, uint32_t a3,
                                         uint32_t b0, uint32_t b1) {
    asm volatile(
        "mma.sync.aligned.m16n8k8.row.col.f32.tf32.tf32.f32 "
        "{%0,%1,%2,%3}, {%4,%5,%6,%7}, {%8,%9}, {%0,%1,%2,%3};"
        : "+f"(c[0]), "+f"(c[1]), "+f"(c[2]), "+f"(c[3])
        : "r"(a0), "r"(a1), "r"(a2), "r"(a3), "r"(b0), "r"(b1));
}
__device__ __forceinline__ uint32_t smem_u32(const void* p) {
    uint32_t a;
    asm("{ .reg .u64 t; cvta.to.shared.u64 t, %1; cvt.u32.u64 %0, t; }"
        : "=r"(a) : "l"(p));
    return a;
}
__device__ __forceinline__ void cpasync16(uint32_t dst, const void* src) {
    asm volatile("cp.async.cg.shared.global [%0], [%1], 16;" :: "r"(dst), "l"(src));
}
// k-permutation within each 32-block: k' = (k%4)*8 + k/4
__device__ __forceinline__ int kperm(int k) {
    const int kb = k >> 5, kl = k & 31;
    return kb * 32 + (kl & 3) * 8 + (kl >> 2);
}

// ============================================================================
// Pre-convert kernels (x and weights; ctx is produced permuted by attn).
// ============================================================================
__global__ void __launch_bounds__(256)
permA0(const float* __restrict__ in)
{
    const int i = blockIdx.x * 256 + threadIdx.x;      // output float4 index
    const int m  = i / (CD / 4);
    const int c4 = i - m * (CD / 4);
    const int kb = c4 >> 3, q = c4 & 7;
    const float* src = in + (size_t)m * CD + kb * 32 + 16 * (q & 1) + (q >> 1);
    uint4 o = { f2tf32(src[0]), f2tf32(src[4]), f2tf32(src[8]), f2tf32(src[12]) };
    reinterpret_cast<uint4*>(g_xp)[i] = o;
}

template <int MODE>
__global__ void transB(const float* __restrict__ W)
{
    uint32_t* __restrict__ out = MODE ? g_wprojp : g_wqkvp;
    const int N = MODE ? CD : CNQKV;
    __shared__ float tile[32][33];
    const int tx = threadIdx.x, ty = threadIdx.y;
    const int nb = blockIdx.x, kb = blockIdx.y;
    #pragma unroll
    for (int r = 0; r < 4; r++) {
        const int kl = ty + 8 * r;
        tile[kl][tx] = W[(size_t)(kb * 32 + kl) * N + nb * 32 + tx];
    }
    __syncthreads();
    const int ksrc = ((tx & 7) << 2) + (tx >> 3);   // inverse perm
    #pragma unroll
    for (int r = 0; r < 4; r++) {
        const int nl = ty + 8 * r;
        out[(size_t)(nb * 32 + nl) * CD + kb * 32 + tx] = f2tf32(tile[ksrc][nl]);
    }
}

// ============================================================================
// tf32 mma.sync GEMM (R9 winner, unchanged except V epilogue -> tf32 g_vp).
// ============================================================================
template <int MODE>
__global__ void __launch_bounds__(128)
gemm_tc3(const float* __restrict__ bias, float* __restrict__ out, int N)
{
    const uint32_t* __restrict__ Ap = MODE ? g_ctxp : g_xp;
    const uint32_t* __restrict__ Bp = MODE ? g_wprojp : g_wqkvp;
    constexpr int K = CD;

    extern __shared__ uint32_t smu[];
    const uint32_t smbase = smem_u32(smu);

    const int tid  = threadIdx.x;
    const int wid  = tid >> 5;
    const int lane = tid & 31;
    const int g    = lane >> 2;
    const int t    = lane & 3;
    const int wm   = wid & 1;
    const int wn   = wid >> 1;
    const int m0   = blockIdx.y * 128;
    const int n0   = blockIdx.x * 128;

    float cf[4][8][4];
    #pragma unroll
    for (int im = 0; im < 4; im++)
        #pragma unroll
        for (int in = 0; in < 8; in++)
            #pragma unroll
            for (int r = 0; r < 4; r++) cf[im][in][r] = 0.f;

    auto issue = [&](int c, int p) {
        const uint32_t abase = smbase + (uint32_t)p * SSTG * 4;
        const uint32_t bbase = abase + 128 * PAW * 4;
        const int k0 = c * 32;
        #pragma unroll
        for (int i = 0; i < 8; i++) {
            const int s = tid + 128 * i;
            const int m = s >> 3, q = s & 7;
            cpasync16(abase + (uint32_t)(m * PAW + q * 4) * 4,
                      Ap + (size_t)(m0 + m) * K + k0 + q * 4);
        }
        #pragma unroll
        for (int i = 0; i < 8; i++) {
            const int s = tid + 128 * i;
            const int n = s >> 3, q = s & 7;
            cpasync16(bbase + (uint32_t)(n * PAW + q * 4) * 4,
                      Bp + (size_t)(n0 + n) * K + k0 + q * 4);
        }
        asm volatile("cp.async.commit_group;" ::: "memory");
    };

    const int NCH = K / 32;   // 40
    issue(0, 0);
    issue(1, 1);

    for (int c = 0; c < NCH; c++) {
        const int p = c % NSTAGE;
        if (c + 1 < NCH) {
            asm volatile("cp.async.wait_group 1;" ::: "memory");
        } else {
            asm volatile("cp.async.wait_group 0;" ::: "memory");
        }
        __syncthreads();

        if (c + 2 < NCH) issue(c + 2, (c + 2) % NSTAGE);

        const uint32_t* As = smu + p * SSTG;
        const uint32_t* Bs = As + 128 * PAW;

        #pragma unroll
        for (int kh = 0; kh < 2; kh++) {
            uint4 a[4][2], b[8];
            #pragma unroll
            for (int im = 0; im < 4; im++) {
                const int row = wm * 64 + im * 16 + g;
                a[im][0] = *reinterpret_cast<const uint4*>(As + row * PAW + t * 8 + kh * 4);
                a[im][1] = *reinterpret_cast<const uint4*>(As + (row + 8) * PAW + t * 8 + kh * 4);
            }
            #pragma unroll
            for (int in = 0; in < 8; in++) {
                const int n = wn * 64 + in * 8 + g;
                b[in] = *reinterpret_cast<const uint4*>(Bs + n * PAW + t * 8 + kh * 4);
            }
            #pragma unroll
            for (int ks2 = 0; ks2 < 2; ks2++) {
                #pragma unroll
                for (int im = 0; im < 4; im++) {
                    const uint32_t a0 = ks2 ? a[im][0].z : a[im][0].x;
                    const uint32_t a2 = ks2 ? a[im][0].w : a[im][0].y;
                    const uint32_t a1 = ks2 ? a[im][1].z : a[im][1].x;
                    const uint32_t a3 = ks2 ? a[im][1].w : a[im][1].y;
                    #pragma unroll
                    for (int in = 0; in < 8; in++) {
                        const uint32_t b0 = ks2 ? b[in].z : b[in].x;
                        const uint32_t b1 = ks2 ? b[in].w : b[in].y;
                        mma_tf32(cf[im][in], a0, a1, a2, a3, b0, b1);
                    }
                }
            }
        }
    }
    __syncthreads();

    // ---- epilogue: +bias; q/k fp32, v tf32, out fp32 ----
    #pragma unroll
    for (int im = 0; im < 4; im++) {
        #pragma unroll
        for (int in = 0; in < 8; in++) {
            const int mrow0 = m0 + wm * 64 + im * 16 + g;
            const int ncol  = n0 + wn * 64 + in * 8 + 2 * t;
            const float2 bb = *reinterpret_cast<const float2*>(bias + ncol);
            #pragma unroll
            for (int h2 = 0; h2 < 2; h2++) {
                const int m = mrow0 + h2 * 8;
                float2 v;
                v.x = cf[im][in][h2 * 2 + 0] + bb.x;
                v.y = cf[im][in][h2 * 2 + 1] + bb.y;
                if (MODE == 0) {
                    const int b = m >> 10;
                    const int s = m & 1023;
                    const int which = ncol / CD;        // 0=q 1=k 2=v
                    const int r = ncol - which * CD;
                    const int h = r / CHD;
                    const int d = r - h * CHD;
                    const size_t di = ((size_t)(b * CH + h) * CS + s) * CHD + d;
                    if (which == 0)      *reinterpret_cast<float2*>(g_q + di) = v;
                    else if (which == 1) *reinterpret_cast<float2*>(g_k + di) = v;
                    else {
                        uint2 u = { f2tf32(v.x), f2tf32(v.y) };
                        *reinterpret_cast<uint2*>(g_vp + di) = u;
                    }
                } else {
                    *reinterpret_cast<float2*>(out + (size_t)m * CD + ncol) = v;
                }
            }
        }
    }
}

// ============================================================================
// RoPE: fp32 q/k -> roped tf32 g_qp (pre-scaled), g_kp.
// ============================================================================
__global__ void __launch_bounds__(256)
rope_kernel(const float* __restrict__ cosb, const float* __restrict__ sinb)
{
    const int idx = blockIdx.x * blockDim.x + threadIdx.x;
    constexpr int TOT = CB * CH * CS * (CHD / 2);
    if (idx >= TOT) return;
    const int d  = idx % (CHD / 2);
    const int s  = (idx / (CHD / 2)) % CS;
    const int bh = idx / ((CHD / 2) * CS);

    const float c  = cosb[s * CHD + d];
    const float sn = sinb[s * CHD + d];
    const size_t base = ((size_t)bh * CS + s) * CHD;

    const float q1 = g_q[base + d], q2 = g_q[base + d + 40];
    g_qp[base + d]      = f2tf32((q1 * c - q2 * sn) * ATTN_SCALE);
    g_qp[base + d + 40] = f2tf32((q2 * c + q1 * sn) * ATTN_SCALE);

    const float k1 = g_k[base + d], k2 = g_k[base + d + 40];
    g_kp[base + d]      = f2tf32(k1 * c - k2 * sn);
    g_kp[base + d + 40] = f2tf32(k2 * c + k1 * sn);
}

// ============================================================================
// Fused flash attention, tf32 mma.sync. All operands arrive pre-converted;
// fills are raw cp.async. K row-major (no transpose). 2 CTAs/SM pinned.
// ============================================================================
__global__ void __launch_bounds__(256, 2)
attn_tc()
{
    extern __shared__ uint32_t smu[];
    uint32_t* Qs = smu;                       // [64][PQ]
    uint32_t* Ks = Qs + 64 * PQ;              // [64][PK2]
    uint32_t* Vs = Ks + 64 * PK2;             // [64][PV]
    float*    Ps = (float*)(Vs + 64 * PV);    // [64][PP]
    float*    sAlpha = Ps + 64 * PP;          // [64]
    float*    sL     = sAlpha + 64;           // [64]
    const uint32_t smb = smem_u32(smu);
    const uint32_t qb = smb;
    const uint32_t kb = smb + 64 * PQ * 4;
    const uint32_t vb = kb + 64 * PK2 * 4;

    const int tid  = threadIdx.x;
    const int wid  = tid >> 5;
    const int lane = tid & 31;
    const int g    = lane >> 2;
    const int t    = lane & 3;
    const int wm   = wid & 1;
    const int wn   = wid >> 1;
    const int wq   = wid & 3;
    const int wd   = wid >> 2;
    const int srow = tid >> 2;
    const int sseg = tid & 3;

    const int bh = blockIdx.y;
    const int q0 = blockIdx.x * 64;

    const uint32_t* __restrict__ Qg = g_qp + (size_t)bh * CS * CHD;
    const uint32_t* __restrict__ Kg = g_kp + (size_t)bh * CS * CHD;
    const uint32_t* __restrict__ Vg = g_vp + (size_t)bh * CS * CHD;

    // Q fill once: 1280 16B-chunks, 5 per thread
    #pragma unroll
    for (int i = 0; i < 5; i++) {
        const int c = tid + 256 * i;
        const int row = c / 20, seg = c % 20;
        cpasync16(qb + (uint32_t)(row * PQ + seg * 4) * 4,
                  Qg + (size_t)(q0 + row) * CHD + seg * 4);
    }
    asm volatile("cp.async.commit_group;" ::: "memory");

    float m_ = -1e30f, l_ = 0.f;
    float of[5][4];
    #pragma unroll
    for (int i = 0; i < 5; i++)
        #pragma unroll
        for (int r = 0; r < 4; r++) of[i][r] = 0.f;

    for (int tt = 0; tt < CS; tt += 64) {
        __syncthreads();   // prev PV done reading Vs/Ps
        #pragma unroll
        for (int i = 0; i < 5; i++) {
            const int c = tid + 256 * i;
            const int row = c / 20, seg = c % 20;
            cpasync16(kb + (uint32_t)(row * PK2 + seg * 4) * 4,
                      Kg + (size_t)(tt + row) * CHD + seg * 4);
            cpasync16(vb + (uint32_t)(row * PV + seg * 4) * 4,
                      Vg + (size_t)(tt + row) * CHD + seg * 4);
        }
        asm volatile("cp.async.commit_group;" ::: "memory");
        asm volatile("cp.async.wait_group 0;" ::: "memory");
        __syncthreads();

        // ---- S = Q K^T (64x64), warp tile 32x16, 10 k8 steps ----
        float sacc[2][2][4];
        #pragma unroll
        for (int im = 0; im < 2; im++)
            #pragma unroll
            for (int in = 0; in < 2; in++)
                #pragma unroll
                for (int r = 0; r < 4; r++) sacc[im][in][r] = 0.f;

        #pragma unroll
        for (int ks = 0; ks < 10; ks++) {
            uint32_t af[2][4], bf[2][2];
            #pragma unroll
            for (int im = 0; im < 2; im++) {
                const int row = wm * 32 + im * 16 + g;
                const int col = ks * 8 + t;
                af[im][0] = Qs[row * PQ + col];
                af[im][1] = Qs[(row + 8) * PQ + col];
                af[im][2] = Qs[row * PQ + col + 4];
                af[im][3] = Qs[(row + 8) * PQ + col + 4];
            }
            #pragma unroll
            for (int in = 0; in < 2; in++) {
                const int n = wn * 16 + in * 8 + g;
                bf[in][0] = Ks[n * PK2 + ks * 8 + t];
                bf[in][1] = Ks[n * PK2 + ks * 8 + t + 4];
            }
            #pragma unroll
            for (int im = 0; im < 2; im++)
                #pragma unroll
                for (int in = 0; in < 2; in++)
                    mma_tf32(sacc[im][in], af[im][0], af[im][1], af[im][2], af[im][3],
                             bf[in][0], bf[in][1]);
        }
        #pragma unroll
        for (int im = 0; im < 2; im++) {
            const int r0 = wm * 32 + im * 16;
            #pragma unroll
            for (int in = 0; in < 2; in++) {
                const int cl = wn * 16 + in * 8 + 2 * t;
                *reinterpret_cast<float2*>(&Ps[(r0 + g) * PP + cl]) =
                    make_float2(sacc[im][in][0], sacc[im][in][1]);
                *reinterpret_cast<float2*>(&Ps[(r0 + g + 8) * PP + cl]) =
                    make_float2(sacc[im][in][2], sacc[im][in][3]);
            }
        }
        __syncthreads();

        // ---- online softmax ----
        {
            float* prow = Ps + srow * PP + sseg * 16;
            float vals[16];
            float mx = -1e30f;
            #pragma unroll
            for (int j = 0; j < 16; j++) { vals[j] = prow[j]; mx = fmaxf(mx, vals[j]); }
            mx = fmaxf(mx, __shfl_xor_sync(0xffffffffu, mx, 1));
            mx = fmaxf(mx, __shfl_xor_sync(0xffffffffu, mx, 2));
            const float mnew  = fmaxf(m_, mx);
            const float alpha = __expf(m_ - mnew);
            float rs = 0.f;
            uint32_t* prow_u = reinterpret_cast<uint32_t*>(prow);
            #pragma unroll
            for (int j = 0; j < 16; j++) {
                const float pj = __expf(vals[j] - mnew);
                rs += pj;
                prow_u[j] = f2tf32(pj);
            }
            rs += __shfl_xor_sync(0xffffffffu, rs, 1);
            rs += __shfl_xor_sync(0xffffffffu, rs, 2);
            l_ = l_ * alpha + rs;
            m_ = mnew;
            if (sseg == 0) sAlpha[srow] = alpha;
        }
        __syncthreads();

        // ---- O = O*alpha + P @ V ----
        {
            const float aL = sAlpha[wq * 16 + g];
            const float aH = sAlpha[wq * 16 + g + 8];
            #pragma unroll
            for (int in = 0; in < 5; in++) {
                of[in][0] *= aL; of[in][1] *= aL;
                of[in][2] *= aH; of[in][3] *= aH;
            }
            const uint32_t* Pu = reinterpret_cast<const uint32_t*>(Ps);
            #pragma unroll
            for (int ks = 0; ks < 8; ks++) {
                const int row = wq * 16 + g;
                const int col = ks * 8 + t;
                uint32_t a0 = Pu[row * PP + col];
                uint32_t a1 = Pu[(row + 8) * PP + col];
                uint32_t a2 = Pu[row * PP + col + 4];
                uint32_t a3 = Pu[(row + 8) * PP + col + 4];
                #pragma unroll
                for (int in = 0; in < 5; in++) {
                    const int n = wd * 40 + in * 8 + g;
                    const uint32_t b0 = Vs[(ks * 8 + t) * PV + n];
                    const uint32_t b1 = Vs[(ks * 8 + t + 4) * PV + n];
                    mma_tf32(of[in], a0, a1, a2, a3, b0, b1);
                }
            }
        }
    }

    // ---- epilogue: write g_ctxp (tf32, k-permuted) ----
    __syncthreads();
    if (sseg == 0) sL[srow] = l_;
    __syncthreads();

    const int b = bh >> 4, h = bh & 15;
    const float invL = 1.f / sL[wq * 16 + g];
    const float invH = 1.f / sL[wq * 16 + g + 8];
    const int rL = q0 + wq * 16 + g;
    const int rH = rL + 8;
    uint32_t* ctxL = g_ctxp + ((size_t)b * CS + rL) * CD;
    uint32_t* ctxH = g_ctxp + ((size_t)b * CS + rH) * CD;
    #pragma unroll
    for (int in = 0; in < 5; in++) {
        const int k0g = h * CHD + wd * 40 + in * 8 + 2 * t;
        const int i0 = kperm(k0g);
        const int i1 = kperm(k0g + 1);
        ctxL[i0] = f2tf32(of[in][0] * invL);
        ctxL[i1] = f2tf32(of[in][1] * invL);
        ctxH[i0] = f2tf32(of[in][2] * invH);
        ctxH[i1] = f2tf32(of[in][3] * invH);
    }
}

// ============================================================================
// launch
// ============================================================================
extern "C" void kernel_launch(void* const* d_in, const int* in_sizes, int n_in,
                              void* d_out, int out_size)
{
    const float* x        = (const float*)d_in[0];
    const float* rope_cos = (const float*)d_in[1];
    const float* rope_sin = (const float*)d_in[2];
    const float* Wqkv     = (const float*)d_in[3];
    const float* bqkv     = (const float*)d_in[4];
    const float* Wproj    = (const float*)d_in[5];
    const float* bproj    = (const float*)d_in[6];
    float* out            = (float*)d_out;

    // 0) pre-convert / permute operands
    permA0<<<CM * CD / 4 / 256, 256>>>(x);
    transB<0><<<dim3(CNQKV / 32, CD / 32), dim3(32, 8)>>>(Wqkv);
    transB<1><<<dim3(CD / 32, CD / 32), dim3(32, 8)>>>(Wproj);

    // 1) QKV projection -> g_q/g_k (fp32), g_vp (tf32)
    cudaFuncSetAttribute(gemm_tc3<0>, cudaFuncAttributeMaxDynamicSharedMemorySize, GEMM_SMEM);
    gemm_tc3<0><<<dim3(CNQKV / 128, CM / 128), 128, GEMM_SMEM>>>(bqkv, nullptr, CNQKV);

    // 2) RoPE -> g_qp (tf32, scaled), g_kp (tf32)
    {
        const int pairs = CB * CH * CS * (CHD / 2);
        rope_kernel<<<(pairs + 255) / 256, 256>>>(rope_cos, rope_sin);
    }

    // 3) fused flash attention -> g_ctxp (tf32, permuted)
    cudaFuncSetAttribute(attn_tc, cudaFuncAttributeMaxDynamicSharedMemorySize, ATTN_SMEM);
    attn_tc<<<dim3(CS / 64, CB * CH), 256, ATTN_SMEM>>>();

    // 4) output projection -> d_out
    cudaFuncSetAttribute(gemm_tc3<1>, cudaFuncAttributeMaxDynamicSharedMemorySize, GEMM_SMEM);
    gemm_tc3<1><<<dim3(CD / 128, CM / 128), 128, GEMM_SMEM>>>(bproj, out, CD);
}